// round 4
// baseline (speedup 1.0000x reference)
#include <cuda_runtime.h>
#include <math.h>

// Problem dims
#define BDIM 32    // batch
#define TDIM 64    // seq len
#define DDIM 32    // n vars / heads
#define HDIM 256   // hidden
#define ZDIM 64    // latent
#define G3   768   // 3*H

// ---- scratch (static device arrays; no allocation) ----
__device__ float g_encGi[BDIM * TDIM * G3];        // [b][t][g]  (6 MB)
__device__ float g_wcomb[DDIM * G3 * DDIM];        // [d][g][i]  (3 MB)
__device__ float g_h0[BDIM * HDIM];                // [b][u]

__device__ __forceinline__ float sigmoidf_(float x) {
    return __fdividef(1.0f, 1.0f + __expf(-x));
}
__device__ __forceinline__ float tanhf_(float x) {
    // tanh(x) = 1 - 2/(e^{2x}+1); exact limits at +-inf via IEEE
    return 1.0f - __fdividef(2.0f, __expf(2.0f * x) + 1.0f);
}

// ============================================================
// Prep 1: encoder input gates  gi[b,t,g] = x_past[b,t,:] . Wih[g,:] + bih[g]
// grid = B*T blocks, 256 threads
// ============================================================
__global__ __launch_bounds__(256) void prep_encgi(
    const float* __restrict__ xp, const float* __restrict__ Wih,
    const float* __restrict__ bih)
{
    __shared__ float xs[DDIM];
    int bt = blockIdx.x;
    int tid = threadIdx.x;
    if (tid < DDIM) xs[tid] = xp[bt * DDIM + tid];
    __syncthreads();
#pragma unroll
    for (int r = 0; r < 3; r++) {
        int g = tid + r * HDIM;
        const float4* w = (const float4*)(Wih + g * DDIM);
        float acc = bih[g];
#pragma unroll
        for (int i4 = 0; i4 < DDIM / 4; i4++) {
            float4 wv = w[i4];
            acc += wv.x * xs[i4 * 4 + 0] + wv.y * xs[i4 * 4 + 1] +
                   wv.z * xs[i4 * 4 + 2] + wv.w * xs[i4 * 4 + 3];
        }
        g_encGi[bt * G3 + g] = acc;
    }
}

// ============================================================
// Prep 2: combined input matrix  W_comb[d][g][i] = sum_h Win[d][i][h]*Wih[d][g][h]
// grid = 32 heads * 96 g-blocks (8 g each), 256 threads
// ============================================================
__global__ __launch_bounds__(256) void prep_wcomb(
    const float* __restrict__ Win, const float* __restrict__ Wih)
{
    int d  = blockIdx.x / 96;
    int gb = blockIdx.x % 96;
    __shared__ float win_s[DDIM * HDIM]; // [i][h] 32 KB
    __shared__ float wih_s[8 * HDIM];    // [gg][h] 8 KB
    int tid = threadIdx.x;
    const float* winp = Win + d * DDIM * HDIM;
    for (int idx = tid; idx < DDIM * HDIM; idx += 256) win_s[idx] = winp[idx];
    const float* wihp = Wih + (d * G3 + gb * 8) * HDIM;
    for (int idx = tid; idx < 8 * HDIM; idx += 256) wih_s[idx] = wihp[idx];
    __syncthreads();
    int gg = tid & 7, i = tid >> 3;
    int rot = tid & (HDIM - 1);
    float acc = 0.0f;
#pragma unroll 8
    for (int h = 0; h < HDIM; h++) {
        int hh = (h + rot) & (HDIM - 1); // lane-rotated for conflict-free LDS
        acc += win_s[i * HDIM + hh] * wih_s[gg * HDIM + hh];
    }
    g_wcomb[(d * G3 + gb * 8 + gg) * DDIM + i] = acc;
}

// ============================================================
// Encoder GRU + VAE head: one CTA per batch element (32 CTAs, 256 threads)
// thread u owns hidden unit u (gate rows u, u+256, u+512)
// ============================================================
__global__ __launch_bounds__(256) void enc_gru(
    const float* __restrict__ Whh,   const float* __restrict__ bhh,
    const float* __restrict__ mu_w,  const float* __restrict__ mu_b,
    const float* __restrict__ ls_w,  const float* __restrict__ ls_b,
    const float* __restrict__ refc_w, const float* __restrict__ refc_b,
    const float* __restrict__ eps,   float* __restrict__ out)
{
    int b = blockIdx.x;
    int u = threadIdx.x;
    __shared__ __align__(16) float h_s[HDIM];
    __shared__ float zv[ZDIM];

    h_s[u] = 0.0f;
    float bhr = bhh[u], bhz = bhh[u + HDIM], bhn = bhh[u + 2 * HDIM];
    const float4* Wr = (const float4*)(Whh + (size_t)u * HDIM);
    const float4* Wz = (const float4*)(Whh + (size_t)(u + HDIM) * HDIM);
    const float4* Wn = (const float4*)(Whh + (size_t)(u + 2 * HDIM) * HDIM);
    __syncthreads();

    for (int t = 0; t < TDIM; t++) {
        const float* gi = g_encGi + (b * TDIM + t) * G3;
        float aR  = gi[u] + bhr;
        float aZ  = gi[u + HDIM] + bhz;
        float aNi = gi[u + 2 * HDIM];
        float aNh = bhn;
        const float4* h4 = (const float4*)h_s;
#pragma unroll 4
        for (int k4 = 0; k4 < HDIM / 4; k4++) {
            float4 hv = h4[k4];
            float4 wr = Wr[k4], wz = Wz[k4], wn = Wn[k4];
            aR  += wr.x * hv.x + wr.y * hv.y + wr.z * hv.z + wr.w * hv.w;
            aZ  += wz.x * hv.x + wz.y * hv.y + wz.z * hv.z + wz.w * hv.w;
            aNh += wn.x * hv.x + wn.y * hv.y + wn.z * hv.z + wn.w * hv.w;
        }
        float r  = sigmoidf_(aR);
        float zz = sigmoidf_(aZ);
        float n  = tanhf_(aNi + r * aNh);
        float hnew = (1.0f - zz) * n + zz * h_s[u];
        __syncthreads();
        h_s[u] = hnew;
        __syncthreads();
    }

    // VAE head
    if (u < ZDIM) {
        const float* mw = mu_w + u * HDIM;
        const float* lw = ls_w + u * HDIM;
        float am = mu_b[u], al = ls_b[u];
#pragma unroll 8
        for (int k = 0; k < HDIM; k++) { am += mw[k] * h_s[k]; al += lw[k] * h_s[k]; }
        out[BDIM * TDIM * DDIM + b * ZDIM + u] = am;                 // mu
        out[BDIM * TDIM * DDIM + BDIM * ZDIM + b * ZDIM + u] = al;   // logsigma
        zv[u] = am + eps[b * ZDIM + u] * __expf(al);
    }
    __syncthreads();
    // h0 = tanh(refc_w @ z + refc_b)
    {
        float acc = refc_b[u];
        const float* rw = refc_w + u * ZDIM;
#pragma unroll 8
        for (int j = 0; j < ZDIM; j++) acc += rw[j] * zv[j];
        g_h0[b * HDIM + u] = tanhf_(acc);
    }
}

// ============================================================
// Decoder: 128 CTAs = 32 heads x 4 batch-slices of 8, 256 threads.
// thread u owns hidden unit u across its 8 batches. Zero inter-CTA sync.
// ============================================================
__global__ __launch_bounds__(256) void dec_gru(
    const float* __restrict__ xp, const float* __restrict__ xc,
    const float* __restrict__ Whh_all, const float* __restrict__ bih_all,
    const float* __restrict__ bhh_all, const float* __restrict__ fcw_all,
    const float* __restrict__ fcb_all, float* __restrict__ out)
{
    int d  = blockIdx.x >> 2;
    int b0 = (blockIdx.x & 3) * 8;
    int tid = threadIdx.x;
    int u = tid;

    __shared__ __align__(16) float h_s[HDIM][8];
    __shared__ __align__(16) float din_s[DDIM][8];
    __shared__ float wsum[8][8];

    const float* Whh = Whh_all + (size_t)d * G3 * HDIM;
    const float* bih = bih_all + d * G3;
    const float* bhh = bhh_all + d * G3;
    float fcw = fcw_all[d * HDIM + u];
    float fcb = fcb_all[d];

    const float4* Wr = (const float4*)(Whh + (size_t)u * HDIM);
    const float4* Wz = (const float4*)(Whh + (size_t)(u + HDIM) * HDIM);
    const float4* Wn = (const float4*)(Whh + (size_t)(u + 2 * HDIM) * HDIM);
    const float* Cw = g_wcomb + (size_t)d * G3 * DDIM;
    const float4* Cr = (const float4*)(Cw + (size_t)u * DDIM);
    const float4* Cz = (const float4*)(Cw + (size_t)(u + HDIM) * DDIM);
    const float4* Cn = (const float4*)(Cw + (size_t)(u + 2 * HDIM) * DDIM);

    float br  = bih[u] + bhh[u];
    float bz  = bih[u + HDIM] + bhh[u + HDIM];
    float bni = bih[u + 2 * HDIM];
    float bnh = bhh[u + 2 * HDIM];

    // init h from h0, stage din for t=0 (x_past[:, -1, :])
    for (int j = tid; j < HDIM * 8; j += 256) {
        int uu = j >> 3, bb = j & 7;
        h_s[uu][bb] = g_h0[(b0 + bb) * HDIM + uu];
    }
    {
        int k = tid >> 3, bb = tid & 7;
        din_s[k][bb] = xp[(b0 + bb) * TDIM * DDIM + (TDIM - 1) * DDIM + k];
    }
    __syncthreads();

    for (int t = 0; t < TDIM; t++) {
        float aR[8], aZ[8], aNi[8], aNh[8];
#pragma unroll
        for (int bb = 0; bb < 8; bb++) { aR[bb] = br; aZ[bb] = bz; aNi[bb] = bni; aNh[bb] = bnh; }

        const float4* h4 = (const float4*)&h_s[0][0];
#pragma unroll 2
        for (int k4 = 0; k4 < HDIM / 4; k4++) {
            float4 wr = Wr[k4], wz = Wz[k4], wn = Wn[k4];
            float wrk[4] = {wr.x, wr.y, wr.z, wr.w};
            float wzk[4] = {wz.x, wz.y, wz.z, wz.w};
            float wnk[4] = {wn.x, wn.y, wn.z, wn.w};
#pragma unroll
            for (int kk = 0; kk < 4; kk++) {
                float4 p = h4[(k4 * 4 + kk) * 2];
                float4 q = h4[(k4 * 4 + kk) * 2 + 1];
                float hv[8] = {p.x, p.y, p.z, p.w, q.x, q.y, q.z, q.w};
#pragma unroll
                for (int bb = 0; bb < 8; bb++) {
                    aR[bb]  += wrk[kk] * hv[bb];
                    aZ[bb]  += wzk[kk] * hv[bb];
                    aNh[bb] += wnk[kk] * hv[bb];
                }
            }
        }
        const float4* d4 = (const float4*)&din_s[0][0];
#pragma unroll
        for (int k4 = 0; k4 < DDIM / 4; k4++) {
            float4 cr = Cr[k4], cz = Cz[k4], cn = Cn[k4];
            float crk[4] = {cr.x, cr.y, cr.z, cr.w};
            float czk[4] = {cz.x, cz.y, cz.z, cz.w};
            float cnk[4] = {cn.x, cn.y, cn.z, cn.w};
#pragma unroll
            for (int kk = 0; kk < 4; kk++) {
                float4 p = d4[(k4 * 4 + kk) * 2];
                float4 q = d4[(k4 * 4 + kk) * 2 + 1];
                float dv[8] = {p.x, p.y, p.z, p.w, q.x, q.y, q.z, q.w};
#pragma unroll
                for (int bb = 0; bb < 8; bb++) {
                    aR[bb]  += crk[kk] * dv[bb];
                    aZ[bb]  += czk[kk] * dv[bb];
                    aNi[bb] += cnk[kk] * dv[bb];
                }
            }
        }

        float hn[8], pr[8];
#pragma unroll
        for (int bb = 0; bb < 8; bb++) {
            float r  = sigmoidf_(aR[bb]);
            float zz = sigmoidf_(aZ[bb]);
            float n  = tanhf_(aNi[bb] + r * aNh[bb]);
            float hold = h_s[u][bb];
            hn[bb] = (1.0f - zz) * n + zz * hold;
            pr[bb] = fcw * hn[bb];
        }
        // fc: reduce fcw*h over 256 units
#pragma unroll
        for (int off = 16; off; off >>= 1) {
#pragma unroll
            for (int bb = 0; bb < 8; bb++)
                pr[bb] += __shfl_xor_sync(0xffffffff, pr[bb], off);
        }
        if ((tid & 31) == 0) {
            int w = tid >> 5;
#pragma unroll
            for (int bb = 0; bb < 8; bb++) wsum[w][bb] = pr[bb];
        }
        __syncthreads();   // all reads of h_s/din_s done; wsum visible

        *(float4*)&h_s[u][0] = make_float4(hn[0], hn[1], hn[2], hn[3]);
        *(float4*)&h_s[u][4] = make_float4(hn[4], hn[5], hn[6], hn[7]);
        if (t + 1 < TDIM) {
            int k = tid >> 3, bb = tid & 7;
            din_s[k][bb] = xc[(b0 + bb) * TDIM * DDIM + t * DDIM + k];
        }
        if (tid < 8) {
            float s = fcb;
#pragma unroll
            for (int w = 0; w < 8; w++) s += wsum[w][tid];
            out[(b0 + tid) * TDIM * DDIM + t * DDIM + d] = s;
        }
        __syncthreads();   // h/din writes visible before next step's reads
    }
}

// ============================================================
// launch
// ============================================================
extern "C" void kernel_launch(void* const* d_in, const int* in_sizes, int n_in,
                              void* d_out, int out_size)
{
    const float* x_past   = (const float*)d_in[0];
    const float* x_current= (const float*)d_in[1];
    const float* eps      = (const float*)d_in[2];
    const float* enc_Wih  = (const float*)d_in[3];
    const float* enc_bih  = (const float*)d_in[4];
    const float* enc_Whh  = (const float*)d_in[5];
    const float* enc_bhh  = (const float*)d_in[6];
    const float* enc_mu_w = (const float*)d_in[7];
    const float* enc_mu_b = (const float*)d_in[8];
    const float* enc_ls_w = (const float*)d_in[9];
    const float* enc_ls_b = (const float*)d_in[10];
    const float* refc_w   = (const float*)d_in[11];
    const float* refc_b   = (const float*)d_in[12];
    const float* Win      = (const float*)d_in[13];
    const float* h_Wih    = (const float*)d_in[14];
    const float* h_bih    = (const float*)d_in[15];
    const float* h_Whh    = (const float*)d_in[16];
    const float* h_bhh    = (const float*)d_in[17];
    const float* fc_w     = (const float*)d_in[18];
    const float* fc_b     = (const float*)d_in[19];
    float* out = (float*)d_out;

    prep_encgi<<<BDIM * TDIM, 256>>>(x_past, enc_Wih, enc_bih);
    prep_wcomb<<<DDIM * 96, 256>>>(Win, h_Wih);
    enc_gru<<<BDIM, 256>>>(enc_Whh, enc_bhh, enc_mu_w, enc_mu_b,
                           enc_ls_w, enc_ls_b, refc_w, refc_b, eps, out);
    dec_gru<<<DDIM * 4, 256>>>(x_past, x_current, h_Whh, h_bih, h_bhh,
                               fc_w, fc_b, out);
}

// round 5
// speedup vs baseline: 1.8738x; 1.8738x over previous
#include <cuda_runtime.h>
#include <math.h>

// Problem dims
#define BDIM 32    // batch
#define TDIM 64    // seq len
#define DDIM 32    // n vars / heads
#define HDIM 256   // hidden
#define ZDIM 64    // latent
#define G3   768   // 3*H

typedef unsigned long long ull;

// ---- scratch (static device arrays; no allocation) ----
__device__ float  g_encGi[BDIM * TDIM * G3];            // [b][t][g]    6 MB
__device__ float  g_h0[BDIM * HDIM];                    // [b][u]
// Transposed decoder recurrent weights: rz pairs + n, coalesced over u
__device__ float4 g_Drz[DDIM * 128 * 256];              // [d][k/2][u] = (r_k,z_k,r_k+1,z_k+1)  16 MB
__device__ float4 g_Dn4[DDIM * 64 * 256];               // [d][k/4][u] = (n_k..n_k+3)            8 MB
// Transposed encoder recurrent weights
__device__ float4 g_Erz[128 * 256];                     // [k/2][u]   512 KB
__device__ float4 g_En4[64 * 256];                      // [k/4][u]   256 KB
// Combined decoder input weights, transposed: [d][i][u]
__device__ float  g_Cr[DDIM * DDIM * 256];              // 1 MB each
__device__ float  g_Cz[DDIM * DDIM * 256];
__device__ float  g_Cn[DDIM * DDIM * 256];

__device__ __forceinline__ float sigmoidf_(float x) {
    return __fdividef(1.0f, 1.0f + __expf(-x));
}
__device__ __forceinline__ float tanhf_(float x) {
    return 1.0f - __fdividef(2.0f, __expf(2.0f * x) + 1.0f);
}
__device__ __forceinline__ void ffma2(ull& d, ull a, ull b) {
    asm("fma.rn.f32x2 %0, %1, %2, %0;" : "+l"(d) : "l"(a), "l"(b));
}
__device__ __forceinline__ ull fadd2(ull a, ull b) {
    ull r; asm("add.rn.f32x2 %0, %1, %2;" : "=l"(r) : "l"(a), "l"(b)); return r;
}
__device__ __forceinline__ ull pk2(float x, float y) {
    ull r; asm("mov.b64 %0, {%1, %2};" : "=l"(r) : "f"(x), "f"(y)); return r;
}
__device__ __forceinline__ float2 upk2(ull v) {
    float2 r; asm("mov.b64 {%0, %1}, %2;" : "=f"(r.x), "=f"(r.y) : "l"(v)); return r;
}

// ============================================================
// Prep 1: encoder input gates  gi[b,t,g] = x_past[b,t,:] . Wih[g,:] + bih[g]
// ============================================================
__global__ __launch_bounds__(256) void prep_encgi(
    const float* __restrict__ xp, const float* __restrict__ Wih,
    const float* __restrict__ bih)
{
    __shared__ float xs[DDIM];
    int bt = blockIdx.x;
    int tid = threadIdx.x;
    if (tid < DDIM) xs[tid] = xp[bt * DDIM + tid];
    __syncthreads();
#pragma unroll
    for (int r = 0; r < 3; r++) {
        int g = tid + r * HDIM;
        const float4* w = (const float4*)(Wih + g * DDIM);
        float acc = bih[g];
#pragma unroll
        for (int i4 = 0; i4 < DDIM / 4; i4++) {
            float4 wv = w[i4];
            acc += wv.x * xs[i4 * 4 + 0] + wv.y * xs[i4 * 4 + 1] +
                   wv.z * xs[i4 * 4 + 2] + wv.w * xs[i4 * 4 + 3];
        }
        g_encGi[bt * G3 + g] = acc;
    }
}

// ============================================================
// Prep 2: transpose recurrent weights W[3H][H] -> rz float4[k/2][256], n float4[k/4][256]
// blockIdx = d*64 + k4 ; 256 threads (u)
// ============================================================
__global__ __launch_bounds__(256) void prep_trans(
    const float* __restrict__ W, float4* __restrict__ rz, float4* __restrict__ n4)
{
    int blk = blockIdx.x;
    int d = blk >> 6, k4 = blk & 63;
    int u = threadIdx.x;
    const float* Wd = W + (size_t)d * G3 * HDIM;
    int k = k4 * 4;
    float4 rr = *(const float4*)(Wd + (size_t)u * HDIM + k);
    float4 zz = *(const float4*)(Wd + (size_t)(u + 256) * HDIM + k);
    float4 nn = *(const float4*)(Wd + (size_t)(u + 512) * HDIM + k);
    rz[((size_t)(d * 128 + k4 * 2 + 0)) * 256 + u] = make_float4(rr.x, zz.x, rr.y, zz.y);
    rz[((size_t)(d * 128 + k4 * 2 + 1)) * 256 + u] = make_float4(rr.z, zz.z, rr.w, zz.w);
    n4[((size_t)(d * 64 + k4)) * 256 + u] = nn;
}

// ============================================================
// Prep 3: combined input matrix, written transposed [d][i][u] per gate
// W_comb[d][g][i] = sum_h Win[d][i][h]*Wih[d][g][h]
// ============================================================
__global__ __launch_bounds__(256) void prep_wcomb(
    const float* __restrict__ Win, const float* __restrict__ Wih)
{
    int d  = blockIdx.x / 96;
    int gb = blockIdx.x % 96;
    __shared__ float win_s[DDIM * HDIM]; // [i][h] 32 KB
    __shared__ float wih_s[8 * HDIM];    // [gg][h] 8 KB
    int tid = threadIdx.x;
    const float* winp = Win + d * DDIM * HDIM;
    for (int idx = tid; idx < DDIM * HDIM; idx += 256) win_s[idx] = winp[idx];
    const float* wihp = Wih + ((size_t)d * G3 + gb * 8) * HDIM;
    for (int idx = tid; idx < 8 * HDIM; idx += 256) wih_s[idx] = wihp[idx];
    __syncthreads();
    int gg = tid & 7, i = tid >> 3;
    int rot = tid & (HDIM - 1);
    float acc = 0.0f;
#pragma unroll 8
    for (int h = 0; h < HDIM; h++) {
        int hh = (h + rot) & (HDIM - 1);
        acc += win_s[i * HDIM + hh] * wih_s[gg * HDIM + hh];
    }
    int g = gb * 8 + gg;
    int gate = g >> 8, uu = g & 255;
    float* dst = gate == 0 ? g_Cr : (gate == 1 ? g_Cz : g_Cn);
    dst[((size_t)d * DDIM + i) * 256 + uu] = acc;
}

// ============================================================
// Encoder GRU + VAE head: one CTA per batch (32 CTAs, 256 threads)
// Coalesced transposed weight loads; (r,z) gates packed in f32x2.
// ============================================================
__global__ __launch_bounds__(256) void enc_gru(
    const float* __restrict__ bhh,
    const float* __restrict__ mu_w,  const float* __restrict__ mu_b,
    const float* __restrict__ ls_w,  const float* __restrict__ ls_b,
    const float* __restrict__ refc_w, const float* __restrict__ refc_b,
    const float* __restrict__ eps,   float* __restrict__ out)
{
    int b = blockIdx.x;
    int u = threadIdx.x;
    __shared__ __align__(16) float h_s[HDIM];
    __shared__ float zv[ZDIM];

    h_s[u] = 0.0f;
    float bhr = bhh[u], bhz = bhh[u + HDIM], bhn = bhh[u + 2 * HDIM];
    const ulonglong2* Erz = (const ulonglong2*)g_Erz;  // [k2][256] of (rz,rz)
    const float4* En = g_En4;                           // [k4][256]
    __syncthreads();

    for (int t = 0; t < TDIM; t++) {
        const float* gi = g_encGi + ((size_t)b * TDIM + t) * G3;
        ull a0 = pk2(gi[u] + bhr, gi[u + HDIM] + bhz);
        ull a1 = 0ull, a2 = 0ull, a3 = 0ull;
        float aNi = gi[u + 2 * HDIM];
        float n0 = bhn, n1 = 0.f, n2 = 0.f, n3 = 0.f;
        const float4* h4p = (const float4*)h_s;
#pragma unroll 8
        for (int k4 = 0; k4 < HDIM / 4; k4++) {
            ulonglong2 rzA = Erz[(k4 * 2 + 0) * 256 + u];
            ulonglong2 rzB = Erz[(k4 * 2 + 1) * 256 + u];
            float4 nn = En[k4 * 256 + u];
            float4 hv = h4p[k4];
            ffma2(a0, rzA.x, pk2(hv.x, hv.x)); n0 = fmaf(nn.x, hv.x, n0);
            ffma2(a1, rzA.y, pk2(hv.y, hv.y)); n1 = fmaf(nn.y, hv.y, n1);
            ffma2(a2, rzB.x, pk2(hv.z, hv.z)); n2 = fmaf(nn.z, hv.z, n2);
            ffma2(a3, rzB.y, pk2(hv.w, hv.w)); n3 = fmaf(nn.w, hv.w, n3);
        }
        float2 arz = upk2(fadd2(fadd2(a0, a1), fadd2(a2, a3)));
        float aNh = (n0 + n1) + (n2 + n3);
        float r  = sigmoidf_(arz.x);
        float zz = sigmoidf_(arz.y);
        float n  = tanhf_(aNi + r * aNh);
        float hnew = (1.0f - zz) * n + zz * h_s[u];
        __syncthreads();
        h_s[u] = hnew;
        __syncthreads();
    }

    // VAE head
    if (u < ZDIM) {
        const float* mw = mu_w + u * HDIM;
        const float* lw = ls_w + u * HDIM;
        float am = mu_b[u], al = ls_b[u];
#pragma unroll 8
        for (int k = 0; k < HDIM; k++) { am += mw[k] * h_s[k]; al += lw[k] * h_s[k]; }
        out[BDIM * TDIM * DDIM + b * ZDIM + u] = am;                 // mu
        out[BDIM * TDIM * DDIM + BDIM * ZDIM + b * ZDIM + u] = al;   // logsigma
        zv[u] = am + eps[b * ZDIM + u] * __expf(al);
    }
    __syncthreads();
    {
        float acc = refc_b[u];
        const float* rw = refc_w + u * ZDIM;
#pragma unroll 8
        for (int j = 0; j < ZDIM; j++) acc += rw[j] * zv[j];
        g_h0[b * HDIM + u] = tanhf_(acc);
    }
}

// ============================================================
// Decoder: 128 CTAs = 32 heads x 4 batch-slices of 8, 256 threads.
// Coalesced transposed weights, f32x2 over batch pairs.
// ============================================================
__global__ __launch_bounds__(256) void dec_gru(
    const float* __restrict__ xp, const float* __restrict__ xc,
    const float* __restrict__ bih_all, const float* __restrict__ bhh_all,
    const float* __restrict__ fcw_all, const float* __restrict__ fcb_all,
    float* __restrict__ out)
{
    int d  = blockIdx.x >> 2;
    int b0 = (blockIdx.x & 3) * 8;
    int tid = threadIdx.x;
    int u = tid;

    __shared__ __align__(16) float h_s[HDIM][8];
    __shared__ __align__(16) float din_s[DDIM][8];
    __shared__ float wsum[8][8];

    const float* bih = bih_all + d * G3;
    const float* bhh = bhh_all + d * G3;
    float fcw = fcw_all[d * HDIM + u];
    float fcb = fcb_all[d];

    const float4* Rz = g_Drz + (size_t)d * 128 * 256 + u;  // step 256 per k2
    const float4* N4 = g_Dn4 + (size_t)d * 64 * 256 + u;   // step 256 per k4
    const float* Cr = g_Cr + (size_t)d * DDIM * 256 + u;   // step 256 per i
    const float* Cz = g_Cz + (size_t)d * DDIM * 256 + u;
    const float* Cn = g_Cn + (size_t)d * DDIM * 256 + u;

    ull br2  = pk2(bih[u] + bhh[u], bih[u] + bhh[u]);
    ull bz2  = pk2(bih[u + HDIM] + bhh[u + HDIM], bih[u + HDIM] + bhh[u + HDIM]);
    ull bni2 = pk2(bih[u + 2 * HDIM], bih[u + 2 * HDIM]);
    ull bnh2 = pk2(bhh[u + 2 * HDIM], bhh[u + 2 * HDIM]);

    // init h from h0, stage din for t=0 (x_past[:, -1, :])
    for (int j = tid; j < HDIM * 8; j += 256) {
        int uu = j >> 3, bb = j & 7;
        h_s[uu][bb] = g_h0[(b0 + bb) * HDIM + uu];
    }
    {
        int k = tid >> 3, bb = tid & 7;
        din_s[k][bb] = xp[((b0 + bb) * TDIM + (TDIM - 1)) * DDIM + k];
    }
    __syncthreads();

    for (int t = 0; t < TDIM; t++) {
        ull aR[4], aZ[4], aNi[4], aNh[4];
#pragma unroll
        for (int p = 0; p < 4; p++) { aR[p] = br2; aZ[p] = bz2; aNi[p] = bni2; aNh[p] = bnh2; }

        // ---- hidden part: k = 0..255 ----
#pragma unroll 8
        for (int k4 = 0; k4 < HDIM / 4; k4++) {
            float4 rzA = Rz[(2 * k4 + 0) * 256];
            float4 rzB = Rz[(2 * k4 + 1) * 256];
            float4 nn  = N4[k4 * 256];
            const ulonglong2* hp = (const ulonglong2*)&h_s[k4 * 4][0];
            {
                ulonglong2 hA = hp[0], hB = hp[1];
                ull wr = pk2(rzA.x, rzA.x), wz = pk2(rzA.y, rzA.y), wn = pk2(nn.x, nn.x);
                ffma2(aR[0], wr, hA.x); ffma2(aR[1], wr, hA.y); ffma2(aR[2], wr, hB.x); ffma2(aR[3], wr, hB.y);
                ffma2(aZ[0], wz, hA.x); ffma2(aZ[1], wz, hA.y); ffma2(aZ[2], wz, hB.x); ffma2(aZ[3], wz, hB.y);
                ffma2(aNh[0], wn, hA.x); ffma2(aNh[1], wn, hA.y); ffma2(aNh[2], wn, hB.x); ffma2(aNh[3], wn, hB.y);
            }
            {
                ulonglong2 hA = hp[2], hB = hp[3];
                ull wr = pk2(rzA.z, rzA.z), wz = pk2(rzA.w, rzA.w), wn = pk2(nn.y, nn.y);
                ffma2(aR[0], wr, hA.x); ffma2(aR[1], wr, hA.y); ffma2(aR[2], wr, hB.x); ffma2(aR[3], wr, hB.y);
                ffma2(aZ[0], wz, hA.x); ffma2(aZ[1], wz, hA.y); ffma2(aZ[2], wz, hB.x); ffma2(aZ[3], wz, hB.y);
                ffma2(aNh[0], wn, hA.x); ffma2(aNh[1], wn, hA.y); ffma2(aNh[2], wn, hB.x); ffma2(aNh[3], wn, hB.y);
            }
            {
                ulonglong2 hA = hp[4], hB = hp[5];
                ull wr = pk2(rzB.x, rzB.x), wz = pk2(rzB.y, rzB.y), wn = pk2(nn.z, nn.z);
                ffma2(aR[0], wr, hA.x); ffma2(aR[1], wr, hA.y); ffma2(aR[2], wr, hB.x); ffma2(aR[3], wr, hB.y);
                ffma2(aZ[0], wz, hA.x); ffma2(aZ[1], wz, hA.y); ffma2(aZ[2], wz, hB.x); ffma2(aZ[3], wz, hB.y);
                ffma2(aNh[0], wn, hA.x); ffma2(aNh[1], wn, hA.y); ffma2(aNh[2], wn, hB.x); ffma2(aNh[3], wn, hB.y);
            }
            {
                ulonglong2 hA = hp[6], hB = hp[7];
                ull wr = pk2(rzB.z, rzB.z), wz = pk2(rzB.w, rzB.w), wn = pk2(nn.w, nn.w);
                ffma2(aR[0], wr, hA.x); ffma2(aR[1], wr, hA.y); ffma2(aR[2], wr, hB.x); ffma2(aR[3], wr, hB.y);
                ffma2(aZ[0], wz, hA.x); ffma2(aZ[1], wz, hA.y); ffma2(aZ[2], wz, hB.x); ffma2(aZ[3], wz, hB.y);
                ffma2(aNh[0], wn, hA.x); ffma2(aNh[1], wn, hA.y); ffma2(aNh[2], wn, hB.x); ffma2(aNh[3], wn, hB.y);
            }
        }

        // ---- input part: i = 0..31 (goes to aNi for the n gate) ----
#pragma unroll 8
        for (int i = 0; i < DDIM; i++) {
            float cr = Cr[i * 256], cz = Cz[i * 256], cn = Cn[i * 256];
            ull wr = pk2(cr, cr), wz = pk2(cz, cz), wn = pk2(cn, cn);
            const ulonglong2* dp = (const ulonglong2*)&din_s[i][0];
            ulonglong2 dA = dp[0], dB = dp[1];
            ffma2(aR[0], wr, dA.x); ffma2(aR[1], wr, dA.y); ffma2(aR[2], wr, dB.x); ffma2(aR[3], wr, dB.y);
            ffma2(aZ[0], wz, dA.x); ffma2(aZ[1], wz, dA.y); ffma2(aZ[2], wz, dB.x); ffma2(aZ[3], wz, dB.y);
            ffma2(aNi[0], wn, dA.x); ffma2(aNi[1], wn, dA.y); ffma2(aNi[2], wn, dB.x); ffma2(aNi[3], wn, dB.y);
        }

        // ---- activations + fc ----
        float4 ho0 = *(const float4*)&h_s[u][0];
        float4 ho1 = *(const float4*)&h_s[u][4];
        float hold[8] = {ho0.x, ho0.y, ho0.z, ho0.w, ho1.x, ho1.y, ho1.z, ho1.w};
        float hn[8], pr[8];
#pragma unroll
        for (int p = 0; p < 4; p++) {
            float2 rr = upk2(aR[p]), zz2 = upk2(aZ[p]);
            float2 ni = upk2(aNi[p]), nh = upk2(aNh[p]);
            float rA = sigmoidf_(rr.x), rB = sigmoidf_(rr.y);
            float uA = sigmoidf_(zz2.x), uB = sigmoidf_(zz2.y);
            float nA = tanhf_(ni.x + rA * nh.x), nB = tanhf_(ni.y + rB * nh.y);
            hn[2 * p]     = (1.0f - uA) * nA + uA * hold[2 * p];
            hn[2 * p + 1] = (1.0f - uB) * nB + uB * hold[2 * p + 1];
            pr[2 * p]     = fcw * hn[2 * p];
            pr[2 * p + 1] = fcw * hn[2 * p + 1];
        }
#pragma unroll
        for (int off = 16; off; off >>= 1) {
#pragma unroll
            for (int bb = 0; bb < 8; bb++)
                pr[bb] += __shfl_xor_sync(0xffffffff, pr[bb], off);
        }
        if ((tid & 31) == 0) {
            int w = tid >> 5;
#pragma unroll
            for (int bb = 0; bb < 8; bb++) wsum[w][bb] = pr[bb];
        }
        __syncthreads();   // all reads of h_s/din_s done; wsum visible

        *(float4*)&h_s[u][0] = make_float4(hn[0], hn[1], hn[2], hn[3]);
        *(float4*)&h_s[u][4] = make_float4(hn[4], hn[5], hn[6], hn[7]);
        if (t + 1 < TDIM) {
            int k = tid >> 3, bb = tid & 7;
            din_s[k][bb] = xc[((b0 + bb) * TDIM + t) * DDIM + k];
        }
        if (tid < 8) {
            float s = fcb;
#pragma unroll
            for (int w = 0; w < 8; w++) s += wsum[w][tid];
            out[((b0 + tid) * TDIM + t) * DDIM + d] = s;
        }
        __syncthreads();   // h/din writes visible before next step's reads
    }
}

// ============================================================
// launch
// ============================================================
extern "C" void kernel_launch(void* const* d_in, const int* in_sizes, int n_in,
                              void* d_out, int out_size)
{
    const float* x_past   = (const float*)d_in[0];
    const float* x_current= (const float*)d_in[1];
    const float* eps      = (const float*)d_in[2];
    const float* enc_Wih  = (const float*)d_in[3];
    const float* enc_bih  = (const float*)d_in[4];
    const float* enc_Whh  = (const float*)d_in[5];
    const float* enc_bhh  = (const float*)d_in[6];
    const float* enc_mu_w = (const float*)d_in[7];
    const float* enc_mu_b = (const float*)d_in[8];
    const float* enc_ls_w = (const float*)d_in[9];
    const float* enc_ls_b = (const float*)d_in[10];
    const float* refc_w   = (const float*)d_in[11];
    const float* refc_b   = (const float*)d_in[12];
    const float* Win      = (const float*)d_in[13];
    const float* h_Wih    = (const float*)d_in[14];
    const float* h_bih    = (const float*)d_in[15];
    const float* h_Whh    = (const float*)d_in[16];
    const float* h_bhh    = (const float*)d_in[17];
    const float* fc_w     = (const float*)d_in[18];
    const float* fc_b     = (const float*)d_in[19];
    float* out = (float*)d_out;

    float4 *dErz, *dEn4, *dDrz, *dDn4;
    cudaGetSymbolAddress((void**)&dErz, g_Erz);
    cudaGetSymbolAddress((void**)&dEn4, g_En4);
    cudaGetSymbolAddress((void**)&dDrz, g_Drz);
    cudaGetSymbolAddress((void**)&dDn4, g_Dn4);

    prep_encgi<<<BDIM * TDIM, 256>>>(x_past, enc_Wih, enc_bih);
    prep_trans<<<64, 256>>>(enc_Whh, dErz, dEn4);
    prep_trans<<<DDIM * 64, 256>>>(h_Whh, dDrz, dDn4);
    prep_wcomb<<<DDIM * 96, 256>>>(Win, h_Wih);
    enc_gru<<<BDIM, 256>>>(enc_bhh, enc_mu_w, enc_mu_b,
                           enc_ls_w, enc_ls_b, refc_w, refc_b, eps, out);
    dec_gru<<<DDIM * 4, 256>>>(x_past, x_current, h_bih, h_bhh,
                               fc_w, fc_b, out);
}

// round 6
// speedup vs baseline: 2.0580x; 1.0983x over previous
#include <cuda_runtime.h>
#include <math.h>
#include <stdint.h>

// Problem dims
#define BDIM 32    // batch
#define TDIM 64    // seq len
#define DDIM 32    // n vars / heads
#define HDIM 256   // hidden
#define ZDIM 64    // latent
#define G3   768   // 3*H

typedef unsigned long long ull;

// ---- scratch (static device arrays; no allocation) ----
__device__ float  g_encGi[BDIM * TDIM * G3];            // [b][t][g]    6 MB
__device__ float  g_h0[BDIM * HDIM];                    // [b][u]
__device__ float  g_hT[BDIM * HDIM];                    // [b][u] final encoder hidden
// Transposed recurrent weights (u-minor, coalesced)
__device__ float4 g_Drz[DDIM * 128 * 256];              // [d][k2][u] = (r_k,z_k,r_k1,z_k1)
__device__ float4 g_Dn4[DDIM * 64 * 256];               // [d][k4][u]
__device__ float4 g_Erz[128 * 256];
__device__ float4 g_En4[64 * 256];
// Combined decoder input weights, transposed: [d][i][u] per gate
__device__ float  g_Cr[DDIM * DDIM * 256];
__device__ float  g_Cz[DDIM * DDIM * 256];
__device__ float  g_Cn[DDIM * DDIM * 256];
// Precomputed decoder input gates: [d][t][g(768)][b(32)]  (201 MB)
__device__ float  g_decGi[(size_t)DDIM * TDIM * G3 * BDIM];

__device__ __forceinline__ float sigmoidf_(float x) {
    return __fdividef(1.0f, 1.0f + __expf(-x));
}
__device__ __forceinline__ float tanhf_(float x) {
    return 1.0f - __fdividef(2.0f, __expf(2.0f * x) + 1.0f);
}
__device__ __forceinline__ void ffma2(ull& d, ull a, ull b) {
    asm("fma.rn.f32x2 %0, %1, %2, %0;" : "+l"(d) : "l"(a), "l"(b));
}
__device__ __forceinline__ ull fadd2(ull a, ull b) {
    ull r; asm("add.rn.f32x2 %0, %1, %2;" : "=l"(r) : "l"(a), "l"(b)); return r;
}
__device__ __forceinline__ ull pk2(float x, float y) {
    ull r; asm("mov.b64 %0, {%1, %2};" : "=l"(r) : "f"(x), "f"(y)); return r;
}
__device__ __forceinline__ float2 upk2(ull v) {
    float2 r; asm("mov.b64 {%0, %1}, %2;" : "=f"(r.x), "=f"(r.y) : "l"(v)); return r;
}
__device__ __forceinline__ uint32_t s2u(const void* p) {
    uint32_t a;
    asm("{ .reg .u64 t; cvta.to.shared.u64 t, %1; cvt.u32.u64 %0, t; }" : "=r"(a) : "l"(p));
    return a;
}
__device__ __forceinline__ uint32_t mapa_(uint32_t laddr, uint32_t rank) {
    uint32_t r;
    asm("mapa.shared::cluster.u32 %0, %1, %2;" : "=r"(r) : "r"(laddr), "r"(rank));
    return r;
}
__device__ __forceinline__ void st_cl64(uint32_t addr, ull v) {
    asm volatile("st.shared::cluster.b64 [%0], %1;" :: "r"(addr), "l"(v) : "memory");
}
__device__ __forceinline__ void cluster_sync_() {
    asm volatile("barrier.cluster.arrive.aligned;" ::: "memory");
    asm volatile("barrier.cluster.wait.aligned;" ::: "memory");
}
__device__ __forceinline__ uint32_t ctarank_() {
    uint32_t r; asm("mov.u32 %0, %%cluster_ctarank;" : "=r"(r)); return r;
}

// ============================================================
// Prep 1: encoder input gates  gi[b,t,g] = x_past[b,t,:] . Wih[g,:] + bih[g]
// ============================================================
__global__ __launch_bounds__(256) void prep_encgi(
    const float* __restrict__ xp, const float* __restrict__ Wih,
    const float* __restrict__ bih)
{
    __shared__ float xs[DDIM];
    int bt = blockIdx.x;
    int tid = threadIdx.x;
    if (tid < DDIM) xs[tid] = xp[bt * DDIM + tid];
    __syncthreads();
#pragma unroll
    for (int r = 0; r < 3; r++) {
        int g = tid + r * HDIM;
        const float4* w = (const float4*)(Wih + g * DDIM);
        float acc = bih[g];
#pragma unroll
        for (int i4 = 0; i4 < DDIM / 4; i4++) {
            float4 wv = w[i4];
            acc += wv.x * xs[i4 * 4 + 0] + wv.y * xs[i4 * 4 + 1] +
                   wv.z * xs[i4 * 4 + 2] + wv.w * xs[i4 * 4 + 3];
        }
        g_encGi[bt * G3 + g] = acc;
    }
}

// ============================================================
// Prep 2: transpose recurrent weights W[3H][H] -> rz float4[k2][256], n float4[k4][256]
// ============================================================
__global__ __launch_bounds__(256) void prep_trans(
    const float* __restrict__ W, float4* __restrict__ rz, float4* __restrict__ n4)
{
    int blk = blockIdx.x;
    int d = blk >> 6, k4 = blk & 63;
    int u = threadIdx.x;
    const float* Wd = W + (size_t)d * G3 * HDIM;
    int k = k4 * 4;
    float4 rr = *(const float4*)(Wd + (size_t)u * HDIM + k);
    float4 zz = *(const float4*)(Wd + (size_t)(u + 256) * HDIM + k);
    float4 nn = *(const float4*)(Wd + (size_t)(u + 512) * HDIM + k);
    rz[((size_t)(d * 128 + k4 * 2 + 0)) * 256 + u] = make_float4(rr.x, zz.x, rr.y, zz.y);
    rz[((size_t)(d * 128 + k4 * 2 + 1)) * 256 + u] = make_float4(rr.z, zz.z, rr.w, zz.w);
    n4[((size_t)(d * 64 + k4)) * 256 + u] = nn;
}

// ============================================================
// Prep 3: combined input matrix, transposed [d][i][u] per gate
// ============================================================
__global__ __launch_bounds__(256) void prep_wcomb(
    const float* __restrict__ Win, const float* __restrict__ Wih)
{
    int d  = blockIdx.x / 96;
    int gb = blockIdx.x % 96;
    __shared__ float win_s[DDIM * HDIM]; // [i][h] 32 KB
    __shared__ float wih_s[8 * HDIM];    // [gg][h] 8 KB
    int tid = threadIdx.x;
    const float* winp = Win + d * DDIM * HDIM;
    for (int idx = tid; idx < DDIM * HDIM; idx += 256) win_s[idx] = winp[idx];
    const float* wihp = Wih + ((size_t)d * G3 + gb * 8) * HDIM;
    for (int idx = tid; idx < 8 * HDIM; idx += 256) wih_s[idx] = wihp[idx];
    __syncthreads();
    int gg = tid & 7, i = tid >> 3;
    float acc0 = 0.0f, acc1 = 0.0f;
#pragma unroll 8
    for (int h = 0; h < HDIM; h += 2) {
        acc0 += win_s[i * HDIM + h]     * wih_s[gg * HDIM + h];
        acc1 += win_s[i * HDIM + h + 1] * wih_s[gg * HDIM + h + 1];
    }
    float acc = acc0 + acc1;
    int g = gb * 8 + gg;
    int gate = g >> 8, uu = g & 255;
    float* dst = gate == 0 ? g_Cr : (gate == 1 ? g_Cz : g_Cn);
    dst[((size_t)d * DDIM + i) * 256 + uu] = acc;
}

// ============================================================
// Prep 4: decoder input gates  g_decGi[d][t][g][b] = sum_i Wcomb[d][g][i]*dec_in[b][t][i]
// grid = d*8 + tblock (256 CTAs), 256 threads. ws SMEM-resident per CTA.
// ============================================================
#define WS_PITCH 33
#define DIN_PITCH 36
__global__ __launch_bounds__(256) void prep_decgi(
    const float* __restrict__ xp, const float* __restrict__ xc)
{
    extern __shared__ char smem_pd[];
    float* ws  = (float*)smem_pd;                       // [768][33]
    float* din = (float*)(smem_pd + G3 * WS_PITCH * 4); // [32][36]
    int d  = blockIdx.x >> 3;
    int tb = blockIdx.x & 7;
    int tid = threadIdx.x;

    // load Wcomb: ws[gate*256+u][i]
    for (int gate = 0; gate < 3; gate++) {
        const float* src = (gate == 0 ? g_Cr : gate == 1 ? g_Cz : g_Cn) + (size_t)d * DDIM * 256;
        for (int i = 0; i < DDIM; i++) {
            ws[(gate * 256 + tid) * WS_PITCH + i] = src[i * 256 + tid];
        }
    }
    __syncthreads();

    for (int tt = 0; tt < 8; tt++) {
        int t = tb * 8 + tt;
        // stage dec_in[:, t, :] transposed: din[i][b]
        {
            const float* src = (t == 0) ? (xp + (size_t)(TDIM - 1) * DDIM)
                                        : (xc + (size_t)(t - 1) * DDIM);
            // src[b] at stride TDIM*DDIM
#pragma unroll
            for (int it = 0; it < 4; it++) {
                int j = it * 256 + tid;
                int b = j >> 5, i = j & 31;
                din[i * DIN_PITCH + b] = src[(size_t)b * TDIM * DDIM + i];
            }
        }
        __syncthreads();
        float* outp = g_decGi + ((size_t)(d * TDIM + t) * G3) * BDIM;
#pragma unroll 4
        for (int k = 0; k < 24; k++) {
            int j4 = k * 256 + tid;
            int g = j4 >> 3;
            int b4 = (j4 & 7) * 4;
            ull a01 = 0ull, a23 = 0ull;
            const float* wrow = ws + g * WS_PITCH;
#pragma unroll 8
            for (int i = 0; i < DDIM; i++) {
                float w = wrow[i];
                ull w2 = pk2(w, w);
                float4 dv = *(const float4*)&din[i * DIN_PITCH + b4];
                ffma2(a01, w2, pk2(dv.x, dv.y));
                ffma2(a23, w2, pk2(dv.z, dv.w));
            }
            float2 r01 = upk2(a01), r23 = upk2(a23);
            *(float4*)(outp + (size_t)g * BDIM + b4) = make_float4(r01.x, r01.y, r23.x, r23.y);
        }
        __syncthreads();
    }
}

// ============================================================
// Encoder GRU: 4 clusters of 4 CTAs (16 CTAs). Cluster c handles batches [c*8, c*8+8).
// CTA rank r owns units [r*64, r*64+64); weights SMEM-resident; h exchanged via DSMEM.
// Writes final hidden to g_hT.
// SMEM: w_rz 128KB | w_n 64KB | h 256*8*4=8KB  => 204800 B
// ============================================================
#define ESM_WN  131072
#define ESM_H   196608
#define ESM_TOT 204800
__global__ __launch_bounds__(256, 1) __cluster_dims__(4, 1, 1)
void enc_gru_cl(const float* __restrict__ bhh)
{
    extern __shared__ char smem_e[];
    float4* w_rz = (float4*)smem_e;            // [k2][64]
    float4* w_n  = (float4*)(smem_e + ESM_WN); // [k4][64]
    float*  h_s  = (float*)(smem_e + ESM_H);   // [256][8]
    int cid = blockIdx.x >> 2;
    uint32_t r = ctarank_();
    int b0 = cid * 8;
    int tid = threadIdx.x;
    int ul = tid >> 2, bg = tid & 3;
    int gr = (int)r * 64 + ul;

    // load weight slice
    for (int i = tid; i < 128 * 64; i += 256) {
        int k2 = i >> 6, uu = i & 63;
        w_rz[k2 * 64 + uu] = g_Erz[k2 * 256 + (int)r * 64 + uu];
    }
    for (int i = tid; i < 64 * 64; i += 256) {
        int k4 = i >> 6, uu = i & 63;
        w_n[k4 * 64 + uu] = g_En4[k4 * 256 + (int)r * 64 + uu];
    }
    for (int i = tid; i < 256 * 8; i += 256) h_s[i] = 0.0f;

    float bhr = bhh[gr], bhz = bhh[gr + HDIM], bhn = bhh[gr + 2 * HDIM];
    float h_old0 = 0.0f, h_old1 = 0.0f;   // this thread's 2 batches

    uint32_t hoff = s2u(&h_s[gr * 8 + bg * 2]);
    uint32_t ra0 = 0, ra1 = 0, ra2 = 0;
    {
        uint32_t tmp[3]; int nr = 0;
        for (uint32_t c = 0; c < 4; c++) if (c != r) tmp[nr++] = mapa_(hoff, c);
        ra0 = tmp[0]; ra1 = tmp[1]; ra2 = tmp[2];
    }
    __syncthreads();

    int bA = b0 + bg * 2, bB = bA + 1;
    for (int t = 0; t < TDIM; t++) {
        const float* giA = g_encGi + ((size_t)bA * TDIM + t) * G3;
        const float* giB = g_encGi + ((size_t)bB * TDIM + t) * G3;
        float gRa = giA[gr], gZa = giA[gr + 256], gNa = giA[gr + 512];
        float gRb = giB[gr], gZb = giB[gr + 256], gNb = giB[gr + 512];

        ull aR[2] = {0ull, 0ull}, aZ[2] = {0ull, 0ull}, aN[2] = {0ull, 0ull};
#pragma unroll 8
        for (int k4 = 0; k4 < 64; k4++) {
            float4 rzA = w_rz[(2 * k4) * 64 + ul];
            float4 rzB = w_rz[(2 * k4 + 1) * 64 + ul];
            float4 nn  = w_n[k4 * 64 + ul];
            const float* hb = &h_s[(k4 * 4) * 8 + bg * 2];
            ull h0 = *(const ull*)(hb);
            ull h1 = *(const ull*)(hb + 8);
            ull h2 = *(const ull*)(hb + 16);
            ull h3 = *(const ull*)(hb + 24);
            ffma2(aR[0], pk2(rzA.x, rzA.x), h0); ffma2(aZ[0], pk2(rzA.y, rzA.y), h0); ffma2(aN[0], pk2(nn.x, nn.x), h0);
            ffma2(aR[1], pk2(rzA.z, rzA.z), h1); ffma2(aZ[1], pk2(rzA.w, rzA.w), h1); ffma2(aN[1], pk2(nn.y, nn.y), h1);
            ffma2(aR[0], pk2(rzB.x, rzB.x), h2); ffma2(aZ[0], pk2(rzB.y, rzB.y), h2); ffma2(aN[0], pk2(nn.z, nn.z), h2);
            ffma2(aR[1], pk2(rzB.z, rzB.z), h3); ffma2(aZ[1], pk2(rzB.w, rzB.w), h3); ffma2(aN[1], pk2(nn.w, nn.w), h3);
        }
        float2 sR = upk2(fadd2(aR[0], aR[1]));
        float2 sZ = upk2(fadd2(aZ[0], aZ[1]));
        float2 sN = upk2(fadd2(aN[0], aN[1]));
        float rA = sigmoidf_(gRa + bhr + sR.x), rB = sigmoidf_(gRb + bhr + sR.y);
        float uA = sigmoidf_(gZa + bhz + sZ.x), uB = sigmoidf_(gZb + bhz + sZ.y);
        float nA = tanhf_(gNa + rA * (sN.x + bhn));
        float nB = tanhf_(gNb + rB * (sN.y + bhn));
        float hnA = (1.0f - uA) * nA + uA * h_old0;
        float hnB = (1.0f - uB) * nB + uB * h_old1;
        h_old0 = hnA; h_old1 = hnB;

        cluster_sync_();             // all reads of h_s done
        ull hv = pk2(hnA, hnB);
        *(ull*)&h_s[gr * 8 + bg * 2] = hv;
        st_cl64(ra0, hv); st_cl64(ra1, hv); st_cl64(ra2, hv);
        cluster_sync_();             // writes visible everywhere
    }
    // write final hidden: rank r writes its 2 batches (full h available locally)
    {
        int b = b0 + (int)r * 2;
        g_hT[(size_t)b * HDIM + tid]       = h_s[tid * 8 + (int)r * 2];
        g_hT[(size_t)(b + 1) * HDIM + tid] = h_s[tid * 8 + (int)r * 2 + 1];
    }
}

// ============================================================
// Encoder head: mu, logsigma, z, h0. grid=B (32), 256 threads.
// ============================================================
__global__ __launch_bounds__(256) void enc_head(
    const float* __restrict__ mu_w,  const float* __restrict__ mu_b,
    const float* __restrict__ ls_w,  const float* __restrict__ ls_b,
    const float* __restrict__ refc_w, const float* __restrict__ refc_b,
    const float* __restrict__ eps,   float* __restrict__ out)
{
    int b = blockIdx.x;
    int u = threadIdx.x;
    __shared__ float hT[HDIM];
    __shared__ float zv[ZDIM];
    hT[u] = g_hT[(size_t)b * HDIM + u];
    __syncthreads();
    if (u < ZDIM) {
        const float* mw = mu_w + u * HDIM;
        const float* lw = ls_w + u * HDIM;
        float am = mu_b[u], al = ls_b[u];
#pragma unroll 8
        for (int k = 0; k < HDIM; k++) { am += mw[k] * hT[k]; al += lw[k] * hT[k]; }
        out[BDIM * TDIM * DDIM + b * ZDIM + u] = am;
        out[BDIM * TDIM * DDIM + BDIM * ZDIM + b * ZDIM + u] = al;
        zv[u] = am + eps[b * ZDIM + u] * __expf(al);
    }
    __syncthreads();
    {
        float acc = refc_b[u];
        const float* rw = refc_w + u * ZDIM;
#pragma unroll 8
        for (int j = 0; j < ZDIM; j++) acc += rw[j] * zv[j];
        g_h0[(size_t)b * HDIM + u] = tanhf_(acc);
    }
}

// ============================================================
// Decoder GRU: 32 clusters of 4 CTAs (128 CTAs). Cluster = head d, rank owns 64 units,
// all 32 batches. Weights SMEM-resident for the whole loop; gi precomputed; h via DSMEM.
// SMEM: w_rz 128K | w_n 64K | h 256*32*4=32K | fcw 1K => 230400 B
// ============================================================
#define DSM_WN  131072
#define DSM_H   196608
#define DSM_FCW 229376
#define DSM_TOT 230400
__global__ __launch_bounds__(256, 1) __cluster_dims__(4, 1, 1)
void dec_gru_cl(
    const float* __restrict__ bih_all, const float* __restrict__ bhh_all,
    const float* __restrict__ fcw_all, const float* __restrict__ fcb_all,
    float* __restrict__ out)
{
    extern __shared__ char smem_d[];
    float4* w_rz = (float4*)smem_d;              // [k2][64]
    float4* w_n  = (float4*)(smem_d + DSM_WN);   // [k4][64]
    float*  h_s  = (float*)(smem_d + DSM_H);     // [256][32]
    float*  fcw_s= (float*)(smem_d + DSM_FCW);   // [256]
    __shared__ float wsum[8][8];

    int d = blockIdx.x >> 2;
    uint32_t r = ctarank_();
    int tid = threadIdx.x;
    int ul = tid >> 2, bg = tid & 3;
    int gr = (int)r * 64 + ul;

    // weights -> SMEM (one-time)
    {
        const float4* src_rz = g_Drz + (size_t)d * 128 * 256;
        for (int i = tid; i < 128 * 64; i += 256) {
            int k2 = i >> 6, uu = i & 63;
            w_rz[k2 * 64 + uu] = src_rz[(size_t)k2 * 256 + (int)r * 64 + uu];
        }
        const float4* src_n = g_Dn4 + (size_t)d * 64 * 256;
        for (int i = tid; i < 64 * 64; i += 256) {
            int k4 = i >> 6, uu = i & 63;
            w_n[k4 * 64 + uu] = src_n[(size_t)k4 * 256 + (int)r * 64 + uu];
        }
        fcw_s[tid] = fcw_all[d * HDIM + tid];
        // full h0 (all 32 batches)
        for (int i = tid; i < 256 * 32; i += 256) {
            int uu = i >> 5, bb = i & 31;
            h_s[uu * 32 + bb] = g_h0[(size_t)bb * HDIM + uu];
        }
    }
    const float* bih = bih_all + d * G3;
    const float* bhh = bhh_all + d * G3;
    float br  = bih[gr] + bhh[gr];
    float bz  = bih[gr + HDIM] + bhh[gr + HDIM];
    float bni = bih[gr + 2 * HDIM];
    float bnh = bhh[gr + 2 * HDIM];
    float fcb = fcb_all[d];

    float hold[8];
#pragma unroll
    for (int bb = 0; bb < 8; bb++) hold[bb] = g_h0[(size_t)(bg * 8 + bb) * HDIM + gr];

    uint32_t hoff = s2u(&h_s[gr * 32 + bg * 8]);
    uint32_t ra0, ra1, ra2;
    {
        uint32_t tmp[3]; int nr = 0;
        for (uint32_t c = 0; c < 4; c++) if (c != r) tmp[nr++] = mapa_(hoff, c);
        ra0 = tmp[0]; ra1 = tmp[1]; ra2 = tmp[2];
    }
    __syncthreads();

    const float* gi_base = g_decGi + ((size_t)d * TDIM * G3) * BDIM + (size_t)gr * BDIM + bg * 8;

    for (int t = 0; t < TDIM; t++) {
        // input-gate values (precomputed), batches bg*8..+7
        const float* gp = gi_base + (size_t)t * G3 * BDIM;
        float4 gR0 = *(const float4*)(gp);
        float4 gR1 = *(const float4*)(gp + 4);
        float4 gZ0 = *(const float4*)(gp + 256 * BDIM);
        float4 gZ1 = *(const float4*)(gp + 256 * BDIM + 4);
        float4 gN0 = *(const float4*)(gp + 512 * BDIM);
        float4 gN1 = *(const float4*)(gp + 512 * BDIM + 4);

        ull aR[4] = {0,0,0,0}, aZ[4] = {0,0,0,0}, aN[4] = {0,0,0,0};
#pragma unroll 8
        for (int k4 = 0; k4 < 64; k4++) {
            float4 rzA = w_rz[(2 * k4) * 64 + ul];
            float4 rzB = w_rz[(2 * k4 + 1) * 64 + ul];
            float4 nn  = w_n[k4 * 64 + ul];
            const ulonglong2* hp0 = (const ulonglong2*)&h_s[(k4 * 4 + 0) * 32 + bg * 8];
            const ulonglong2* hp1 = (const ulonglong2*)&h_s[(k4 * 4 + 1) * 32 + bg * 8];
            const ulonglong2* hp2 = (const ulonglong2*)&h_s[(k4 * 4 + 2) * 32 + bg * 8];
            const ulonglong2* hp3 = (const ulonglong2*)&h_s[(k4 * 4 + 3) * 32 + bg * 8];
            {
                ulonglong2 hA = hp0[0], hB = hp0[1];
                ull wr = pk2(rzA.x, rzA.x), wz = pk2(rzA.y, rzA.y), wn = pk2(nn.x, nn.x);
                ffma2(aR[0], wr, hA.x); ffma2(aR[1], wr, hA.y); ffma2(aR[2], wr, hB.x); ffma2(aR[3], wr, hB.y);
                ffma2(aZ[0], wz, hA.x); ffma2(aZ[1], wz, hA.y); ffma2(aZ[2], wz, hB.x); ffma2(aZ[3], wz, hB.y);
                ffma2(aN[0], wn, hA.x); ffma2(aN[1], wn, hA.y); ffma2(aN[2], wn, hB.x); ffma2(aN[3], wn, hB.y);
            }
            {
                ulonglong2 hA = hp1[0], hB = hp1[1];
                ull wr = pk2(rzA.z, rzA.z), wz = pk2(rzA.w, rzA.w), wn = pk2(nn.y, nn.y);
                ffma2(aR[0], wr, hA.x); ffma2(aR[1], wr, hA.y); ffma2(aR[2], wr, hB.x); ffma2(aR[3], wr, hB.y);
                ffma2(aZ[0], wz, hA.x); ffma2(aZ[1], wz, hA.y); ffma2(aZ[2], wz, hB.x); ffma2(aZ[3], wz, hB.y);
                ffma2(aN[0], wn, hA.x); ffma2(aN[1], wn, hA.y); ffma2(aN[2], wn, hB.x); ffma2(aN[3], wn, hB.y);
            }
            {
                ulonglong2 hA = hp2[0], hB = hp2[1];
                ull wr = pk2(rzB.x, rzB.x), wz = pk2(rzB.y, rzB.y), wn = pk2(nn.z, nn.z);
                ffma2(aR[0], wr, hA.x); ffma2(aR[1], wr, hA.y); ffma2(aR[2], wr, hB.x); ffma2(aR[3], wr, hB.y);
                ffma2(aZ[0], wz, hA.x); ffma2(aZ[1], wz, hA.y); ffma2(aZ[2], wz, hB.x); ffma2(aZ[3], wz, hB.y);
                ffma2(aN[0], wn, hA.x); ffma2(aN[1], wn, hA.y); ffma2(aN[2], wn, hB.x); ffma2(aN[3], wn, hB.y);
            }
            {
                ulonglong2 hA = hp3[0], hB = hp3[1];
                ull wr = pk2(rzB.z, rzB.z), wz = pk2(rzB.w, rzB.w), wn = pk2(nn.w, nn.w);
                ffma2(aR[0], wr, hA.x); ffma2(aR[1], wr, hA.y); ffma2(aR[2], wr, hB.x); ffma2(aR[3], wr, hB.y);
                ffma2(aZ[0], wz, hA.x); ffma2(aZ[1], wz, hA.y); ffma2(aZ[2], wz, hB.x); ffma2(aZ[3], wz, hB.y);
                ffma2(aN[0], wn, hA.x); ffma2(aN[1], wn, hA.y); ffma2(aN[2], wn, hB.x); ffma2(aN[3], wn, hB.y);
            }
        }

        // activations for 8 batches
        float gR[8] = {gR0.x,gR0.y,gR0.z,gR0.w,gR1.x,gR1.y,gR1.z,gR1.w};
        float gZ[8] = {gZ0.x,gZ0.y,gZ0.z,gZ0.w,gZ1.x,gZ1.y,gZ1.z,gZ1.w};
        float gN[8] = {gN0.x,gN0.y,gN0.z,gN0.w,gN1.x,gN1.y,gN1.z,gN1.w};
        float hn[8];
#pragma unroll
        for (int p = 0; p < 4; p++) {
            float2 sR = upk2(aR[p]), sZ = upk2(aZ[p]), sN = upk2(aN[p]);
            float rA = sigmoidf_(gR[2*p]   + br + sR.x);
            float rB = sigmoidf_(gR[2*p+1] + br + sR.y);
            float uA = sigmoidf_(gZ[2*p]   + bz + sZ.x);
            float uB = sigmoidf_(gZ[2*p+1] + bz + sZ.y);
            float nA = tanhf_(gN[2*p]   + bni + rA * (sN.x + bnh));
            float nB = tanhf_(gN[2*p+1] + bni + rB * (sN.y + bnh));
            hn[2*p]   = (1.0f - uA) * nA + uA * hold[2*p];
            hn[2*p+1] = (1.0f - uB) * nB + uB * hold[2*p+1];
        }
#pragma unroll
        for (int bb = 0; bb < 8; bb++) hold[bb] = hn[bb];

        cluster_sync_();   // everyone done reading h_s
        ull h01 = pk2(hn[0], hn[1]), h23 = pk2(hn[2], hn[3]);
        ull h45 = pk2(hn[4], hn[5]), h67 = pk2(hn[6], hn[7]);
        ull* lp = (ull*)&h_s[gr * 32 + bg * 8];
        lp[0] = h01; lp[1] = h23; lp[2] = h45; lp[3] = h67;
        st_cl64(ra0,      h01); st_cl64(ra0 + 8,  h23); st_cl64(ra0 + 16, h45); st_cl64(ra0 + 24, h67);
        st_cl64(ra1,      h01); st_cl64(ra1 + 8,  h23); st_cl64(ra1 + 16, h45); st_cl64(ra1 + 24, h67);
        st_cl64(ra2,      h01); st_cl64(ra2 + 8,  h23); st_cl64(ra2 + 16, h45); st_cl64(ra2 + 24, h67);
        cluster_sync_();   // h_new visible everywhere

        // fc output: rank handles batches r*8..r*8+7 over full h
        {
            float4 ha = *(const float4*)&h_s[tid * 32 + (int)r * 8];
            float4 hb = *(const float4*)&h_s[tid * 32 + (int)r * 8 + 4];
            float pr[8] = {ha.x, ha.y, ha.z, ha.w, hb.x, hb.y, hb.z, hb.w};
            float fw = fcw_s[tid];
#pragma unroll
            for (int bb = 0; bb < 8; bb++) pr[bb] *= fw;
#pragma unroll
            for (int off = 16; off; off >>= 1) {
#pragma unroll
                for (int bb = 0; bb < 8; bb++)
                    pr[bb] += __shfl_xor_sync(0xffffffff, pr[bb], off);
            }
            if ((tid & 31) == 0) {
                int w = tid >> 5;
#pragma unroll
                for (int bb = 0; bb < 8; bb++) wsum[w][bb] = pr[bb];
            }
            __syncthreads();
            if (tid < 8) {
                float s = fcb;
#pragma unroll
                for (int w = 0; w < 8; w++) s += wsum[w][tid];
                int b = (int)r * 8 + tid;
                out[((size_t)b * TDIM + t) * DDIM + d] = s;
            }
        }
    }
}

// ============================================================
// launch
// ============================================================
extern "C" void kernel_launch(void* const* d_in, const int* in_sizes, int n_in,
                              void* d_out, int out_size)
{
    const float* x_past   = (const float*)d_in[0];
    const float* x_current= (const float*)d_in[1];
    const float* eps      = (const float*)d_in[2];
    const float* enc_Wih  = (const float*)d_in[3];
    const float* enc_bih  = (const float*)d_in[4];
    const float* enc_Whh  = (const float*)d_in[5];
    const float* enc_bhh  = (const float*)d_in[6];
    const float* enc_mu_w = (const float*)d_in[7];
    const float* enc_mu_b = (const float*)d_in[8];
    const float* enc_ls_w = (const float*)d_in[9];
    const float* enc_ls_b = (const float*)d_in[10];
    const float* refc_w   = (const float*)d_in[11];
    const float* refc_b   = (const float*)d_in[12];
    const float* Win      = (const float*)d_in[13];
    const float* h_Wih    = (const float*)d_in[14];
    const float* h_bih    = (const float*)d_in[15];
    const float* h_Whh    = (const float*)d_in[16];
    const float* h_bhh    = (const float*)d_in[17];
    const float* fc_w     = (const float*)d_in[18];
    const float* fc_b     = (const float*)d_in[19];
    float* out = (float*)d_out;

    float4 *dErz, *dEn4, *dDrz, *dDn4;
    cudaGetSymbolAddress((void**)&dErz, g_Erz);
    cudaGetSymbolAddress((void**)&dEn4, g_En4);
    cudaGetSymbolAddress((void**)&dDrz, g_Drz);
    cudaGetSymbolAddress((void**)&dDn4, g_Dn4);

    static int attr_done = 0;
    if (!attr_done) {
        cudaFuncSetAttribute(prep_decgi, cudaFuncAttributeMaxDynamicSharedMemorySize,
                             G3 * WS_PITCH * 4 + DDIM * DIN_PITCH * 4);
        cudaFuncSetAttribute(enc_gru_cl, cudaFuncAttributeMaxDynamicSharedMemorySize, ESM_TOT);
        cudaFuncSetAttribute(dec_gru_cl, cudaFuncAttributeMaxDynamicSharedMemorySize, DSM_TOT);
        attr_done = 1;
    }

    prep_encgi<<<BDIM * TDIM, 256>>>(x_past, enc_Wih, enc_bih);
    prep_trans<<<64, 256>>>(enc_Whh, dErz, dEn4);
    prep_trans<<<DDIM * 64, 256>>>(h_Whh, dDrz, dDn4);
    prep_wcomb<<<DDIM * 96, 256>>>(Win, h_Wih);
    prep_decgi<<<DDIM * 8, 256, G3 * WS_PITCH * 4 + DDIM * DIN_PITCH * 4>>>(x_past, x_current);
    enc_gru_cl<<<16, 256, ESM_TOT>>>(enc_bhh);
    enc_head<<<BDIM, 256>>>(enc_mu_w, enc_mu_b, enc_ls_w, enc_ls_b,
                            refc_w, refc_b, eps, out);
    dec_gru_cl<<<DDIM * 4, 256, DSM_TOT>>>(h_bih, h_bhh, fc_w, fc_b, out);
}

// round 7
// speedup vs baseline: 2.7169x; 1.3202x over previous
#include <cuda_runtime.h>
#include <math.h>
#include <stdint.h>

// Problem dims
#define BDIM 32    // batch
#define TDIM 64    // seq len
#define DDIM 32    // n vars / heads
#define HDIM 256   // hidden
#define ZDIM 64    // latent
#define G3   768   // 3*H

typedef unsigned long long ull;

// ---- scratch (static device arrays; no allocation) ----
__device__ float  g_encGi[BDIM * TDIM * G3];            // [b][t][g]    6 MB
__device__ float  g_h0[BDIM * HDIM];                    // [b][u]
__device__ float  g_hT[BDIM * HDIM];                    // [b][u] final encoder hidden
// Transposed recurrent weights (u-minor, coalesced)
__device__ float4 g_Drz[DDIM * 128 * 256];              // [d][k2][u] = (r_k,z_k,r_k1,z_k1)
__device__ float4 g_Dn4[DDIM * 64 * 256];               // [d][k4][u]
__device__ float4 g_Erz[128 * 256];
__device__ float4 g_En4[64 * 256];
// Combined decoder input weights, transposed: [d][i][u] per gate
__device__ float  g_Cr[DDIM * DDIM * 256];
__device__ float  g_Cz[DDIM * DDIM * 256];
__device__ float  g_Cn[DDIM * DDIM * 256];
// Precomputed decoder input gates: [d][t][g(768)][b(32)]  (201 MB)
__device__ float  g_decGi[(size_t)DDIM * TDIM * G3 * BDIM];

__device__ __forceinline__ float sigmoidf_(float x) {
    return __fdividef(1.0f, 1.0f + __expf(-x));
}
__device__ __forceinline__ float tanhf_(float x) {
    return 1.0f - __fdividef(2.0f, __expf(2.0f * x) + 1.0f);
}
__device__ __forceinline__ void ffma2(ull& d, ull a, ull b) {
    asm("fma.rn.f32x2 %0, %1, %2, %0;" : "+l"(d) : "l"(a), "l"(b));
}
__device__ __forceinline__ ull fadd2(ull a, ull b) {
    ull r; asm("add.rn.f32x2 %0, %1, %2;" : "=l"(r) : "l"(a), "l"(b)); return r;
}
__device__ __forceinline__ ull pk2(float x, float y) {
    ull r; asm("mov.b64 %0, {%1, %2};" : "=l"(r) : "f"(x), "f"(y)); return r;
}
__device__ __forceinline__ float2 upk2(ull v) {
    float2 r; asm("mov.b64 {%0, %1}, %2;" : "=f"(r.x), "=f"(r.y) : "l"(v)); return r;
}
__device__ __forceinline__ uint32_t s2u(const void* p) {
    uint32_t a;
    asm("{ .reg .u64 t; cvta.to.shared.u64 t, %1; cvt.u32.u64 %0, t; }" : "=r"(a) : "l"(p));
    return a;
}
__device__ __forceinline__ uint32_t mapa_(uint32_t laddr, uint32_t rank) {
    uint32_t r;
    asm("mapa.shared::cluster.u32 %0, %1, %2;" : "=r"(r) : "r"(laddr), "r"(rank));
    return r;
}
__device__ __forceinline__ void st_cl64(uint32_t addr, ull v) {
    asm volatile("st.shared::cluster.b64 [%0], %1;" :: "r"(addr), "l"(v) : "memory");
}
__device__ __forceinline__ void cluster_sync_() {
    asm volatile("barrier.cluster.arrive.aligned;" ::: "memory");
    asm volatile("barrier.cluster.wait.aligned;" ::: "memory");
}
__device__ __forceinline__ uint32_t ctarank_() {
    uint32_t r; asm("mov.u32 %0, %%cluster_ctarank;" : "=r"(r)); return r;
}

// ============================================================
// Prep 1: encoder input gates  gi[b,t,g] = x_past[b,t,:] . Wih[g,:] + bih[g]
// ============================================================
__global__ __launch_bounds__(256) void prep_encgi(
    const float* __restrict__ xp, const float* __restrict__ Wih,
    const float* __restrict__ bih)
{
    __shared__ float xs[DDIM];
    int bt = blockIdx.x;
    int tid = threadIdx.x;
    if (tid < DDIM) xs[tid] = xp[bt * DDIM + tid];
    __syncthreads();
#pragma unroll
    for (int r = 0; r < 3; r++) {
        int g = tid + r * HDIM;
        const float4* w = (const float4*)(Wih + g * DDIM);
        float acc = bih[g];
#pragma unroll
        for (int i4 = 0; i4 < DDIM / 4; i4++) {
            float4 wv = w[i4];
            acc += wv.x * xs[i4 * 4 + 0] + wv.y * xs[i4 * 4 + 1] +
                   wv.z * xs[i4 * 4 + 2] + wv.w * xs[i4 * 4 + 3];
        }
        g_encGi[bt * G3 + g] = acc;
    }
}

// ============================================================
// Prep 2: transpose recurrent weights W[3H][H] -> rz float4[k2][256], n float4[k4][256]
// ============================================================
__global__ __launch_bounds__(256) void prep_trans(
    const float* __restrict__ W, float4* __restrict__ rz, float4* __restrict__ n4)
{
    int blk = blockIdx.x;
    int d = blk >> 6, k4 = blk & 63;
    int u = threadIdx.x;
    const float* Wd = W + (size_t)d * G3 * HDIM;
    int k = k4 * 4;
    float4 rr = *(const float4*)(Wd + (size_t)u * HDIM + k);
    float4 zz = *(const float4*)(Wd + (size_t)(u + 256) * HDIM + k);
    float4 nn = *(const float4*)(Wd + (size_t)(u + 512) * HDIM + k);
    rz[((size_t)(d * 128 + k4 * 2 + 0)) * 256 + u] = make_float4(rr.x, zz.x, rr.y, zz.y);
    rz[((size_t)(d * 128 + k4 * 2 + 1)) * 256 + u] = make_float4(rr.z, zz.z, rr.w, zz.w);
    n4[((size_t)(d * 64 + k4)) * 256 + u] = nn;
}

// ============================================================
// Prep 3: combined input matrix, transposed [d][i][u] per gate
// Conflict-free: pitch 258 so banks = (2i+h)%32 / (2gg+h)%32 (all distinct per warp)
// ============================================================
#define PW_PITCH 258
__global__ __launch_bounds__(256) void prep_wcomb(
    const float* __restrict__ Win, const float* __restrict__ Wih)
{
    int d  = blockIdx.x / 96;
    int gb = blockIdx.x % 96;
    __shared__ __align__(16) float win_s[DDIM * PW_PITCH]; // [i][h] padded
    __shared__ __align__(16) float wih_s[8 * PW_PITCH];    // [gg][h] padded
    int tid = threadIdx.x;
    const float* winp = Win + (size_t)d * DDIM * HDIM;
    for (int idx = tid; idx < DDIM * HDIM; idx += 256) {
        int i = idx >> 8, h = idx & 255;
        win_s[i * PW_PITCH + h] = winp[idx];
    }
    const float* wihp = Wih + ((size_t)d * G3 + gb * 8) * HDIM;
    for (int idx = tid; idx < 8 * HDIM; idx += 256) {
        int gg = idx >> 8, h = idx & 255;
        wih_s[gg * PW_PITCH + h] = wihp[idx];
    }
    __syncthreads();
    int gg = tid & 7, i = tid >> 3;
    const ull* wp = (const ull*)&win_s[i * PW_PITCH];
    const ull* gp = (const ull*)&wih_s[gg * PW_PITCH];
    ull acc = 0ull;
#pragma unroll 8
    for (int h2 = 0; h2 < HDIM / 2; h2++) {
        ffma2(acc, wp[h2], gp[h2]);
    }
    float2 a2 = upk2(acc);
    float acc_s = a2.x + a2.y;
    int g = gb * 8 + gg;
    int gate = g >> 8, uu = g & 255;
    float* dst = gate == 0 ? g_Cr : (gate == 1 ? g_Cz : g_Cn);
    dst[((size_t)d * DDIM + i) * 256 + uu] = acc_s;
}

// ============================================================
// Prep 4: decoder input gates  g_decGi[d][t][g][b] = sum_i Wcomb[d][g][i]*dec_in[b][t][i]
// ============================================================
#define WS_PITCH 33
#define DIN_PITCH 36
__global__ __launch_bounds__(256) void prep_decgi(
    const float* __restrict__ xp, const float* __restrict__ xc)
{
    extern __shared__ char smem_pd[];
    float* ws  = (float*)smem_pd;                       // [768][33]
    float* din = (float*)(smem_pd + G3 * WS_PITCH * 4); // [32][36]
    int d  = blockIdx.x >> 3;
    int tb = blockIdx.x & 7;
    int tid = threadIdx.x;

    for (int gate = 0; gate < 3; gate++) {
        const float* src = (gate == 0 ? g_Cr : gate == 1 ? g_Cz : g_Cn) + (size_t)d * DDIM * 256;
        for (int i = 0; i < DDIM; i++) {
            ws[(gate * 256 + tid) * WS_PITCH + i] = src[i * 256 + tid];
        }
    }
    __syncthreads();

    for (int tt = 0; tt < 8; tt++) {
        int t = tb * 8 + tt;
        {
            const float* src = (t == 0) ? (xp + (size_t)(TDIM - 1) * DDIM)
                                        : (xc + (size_t)(t - 1) * DDIM);
#pragma unroll
            for (int it = 0; it < 4; it++) {
                int j = it * 256 + tid;
                int b = j >> 5, i = j & 31;
                din[i * DIN_PITCH + b] = src[(size_t)b * TDIM * DDIM + i];
            }
        }
        __syncthreads();
        float* outp = g_decGi + ((size_t)(d * TDIM + t) * G3) * BDIM;
#pragma unroll 4
        for (int k = 0; k < 24; k++) {
            int j4 = k * 256 + tid;
            int g = j4 >> 3;
            int b4 = (j4 & 7) * 4;
            ull a01 = 0ull, a23 = 0ull;
            const float* wrow = ws + g * WS_PITCH;
#pragma unroll 8
            for (int i = 0; i < DDIM; i++) {
                float w = wrow[i];
                ull w2 = pk2(w, w);
                float4 dv = *(const float4*)&din[i * DIN_PITCH + b4];
                ffma2(a01, w2, pk2(dv.x, dv.y));
                ffma2(a23, w2, pk2(dv.z, dv.w));
            }
            float2 r01 = upk2(a01), r23 = upk2(a23);
            *(float4*)(outp + (size_t)g * BDIM + b4) = make_float4(r01.x, r01.y, r23.x, r23.y);
        }
        __syncthreads();
    }
}

// ============================================================
// Encoder GRU: 4 clusters of 4 CTAs. Double-buffered h -> ONE cluster_sync/step.
// SMEM: w_rz 128KB | w_n 64KB | h0 8KB | h1 8KB => 212992 B
// ============================================================
#define ESM_WN  131072
#define ESM_H0  196608
#define ESM_H1  204800
#define ESM_TOT 212992
__global__ __launch_bounds__(256, 1) __cluster_dims__(4, 1, 1)
void enc_gru_cl(const float* __restrict__ bhh)
{
    extern __shared__ char smem_e[];
    float4* w_rz = (float4*)smem_e;            // [k2][64]
    float4* w_n  = (float4*)(smem_e + ESM_WN); // [k4][64]
    float*  hbuf0 = (float*)(smem_e + ESM_H0); // [256][8]
    float*  hbuf1 = (float*)(smem_e + ESM_H1); // [256][8]
    int cid = blockIdx.x >> 2;
    uint32_t r = ctarank_();
    int b0 = cid * 8;
    int tid = threadIdx.x;
    int ul = tid >> 2, bg = tid & 3;
    int gr = (int)r * 64 + ul;

    for (int i = tid; i < 128 * 64; i += 256) {
        int k2 = i >> 6, uu = i & 63;
        w_rz[k2 * 64 + uu] = g_Erz[k2 * 256 + (int)r * 64 + uu];
    }
    for (int i = tid; i < 64 * 64; i += 256) {
        int k4 = i >> 6, uu = i & 63;
        w_n[k4 * 64 + uu] = g_En4[k4 * 256 + (int)r * 64 + uu];
    }
    for (int i = tid; i < 256 * 8; i += 256) hbuf0[i] = 0.0f;

    float bhr = bhh[gr], bhz = bhh[gr + HDIM], bhn = bhh[gr + 2 * HDIM];
    float h_old0 = 0.0f, h_old1 = 0.0f;

    uint32_t hoff0 = s2u(&hbuf0[gr * 8 + bg * 2]);
    uint32_t ra0 = 0, ra1 = 0, ra2 = 0;
    {
        uint32_t tmp[3]; int nr = 0;
        for (uint32_t c = 0; c < 4; c++) if (c != r) tmp[nr++] = mapa_(hoff0, c);
        ra0 = tmp[0]; ra1 = tmp[1]; ra2 = tmp[2];
    }
    __syncthreads();

    int bA = b0 + bg * 2, bB = bA + 1;
    int p = 0;
    for (int t = 0; t < TDIM; t++) {
        const float* hr = p ? hbuf1 : hbuf0;
        const float* giA = g_encGi + ((size_t)bA * TDIM + t) * G3;
        const float* giB = g_encGi + ((size_t)bB * TDIM + t) * G3;
        float gRa = giA[gr], gZa = giA[gr + 256], gNa = giA[gr + 512];
        float gRb = giB[gr], gZb = giB[gr + 256], gNb = giB[gr + 512];

        ull aR[2] = {0ull, 0ull}, aZ[2] = {0ull, 0ull}, aN[2] = {0ull, 0ull};
#pragma unroll 8
        for (int k4 = 0; k4 < 64; k4++) {
            float4 rzA = w_rz[(2 * k4) * 64 + ul];
            float4 rzB = w_rz[(2 * k4 + 1) * 64 + ul];
            float4 nn  = w_n[k4 * 64 + ul];
            const float* hb = &hr[(k4 * 4) * 8 + bg * 2];
            ull h0 = *(const ull*)(hb);
            ull h1 = *(const ull*)(hb + 8);
            ull h2 = *(const ull*)(hb + 16);
            ull h3 = *(const ull*)(hb + 24);
            ffma2(aR[0], pk2(rzA.x, rzA.x), h0); ffma2(aZ[0], pk2(rzA.y, rzA.y), h0); ffma2(aN[0], pk2(nn.x, nn.x), h0);
            ffma2(aR[1], pk2(rzA.z, rzA.z), h1); ffma2(aZ[1], pk2(rzA.w, rzA.w), h1); ffma2(aN[1], pk2(nn.y, nn.y), h1);
            ffma2(aR[0], pk2(rzB.x, rzB.x), h2); ffma2(aZ[0], pk2(rzB.y, rzB.y), h2); ffma2(aN[0], pk2(nn.z, nn.z), h2);
            ffma2(aR[1], pk2(rzB.z, rzB.z), h3); ffma2(aZ[1], pk2(rzB.w, rzB.w), h3); ffma2(aN[1], pk2(nn.w, nn.w), h3);
        }
        float2 sR = upk2(fadd2(aR[0], aR[1]));
        float2 sZ = upk2(fadd2(aZ[0], aZ[1]));
        float2 sN = upk2(fadd2(aN[0], aN[1]));
        float rA = sigmoidf_(gRa + bhr + sR.x), rB = sigmoidf_(gRb + bhr + sR.y);
        float uA = sigmoidf_(gZa + bhz + sZ.x), uB = sigmoidf_(gZb + bhz + sZ.y);
        float nA = tanhf_(gNa + rA * (sN.x + bhn));
        float nB = tanhf_(gNb + rB * (sN.y + bhn));
        float hnA = (1.0f - uA) * nA + uA * h_old0;
        float hnB = (1.0f - uB) * nB + uB * h_old1;
        h_old0 = hnA; h_old1 = hnB;

        // write new h into the OTHER buffer; one barrier publishes it
        float* hw = p ? hbuf0 : hbuf1;
        uint32_t roff = p ? 0u : 8192u;
        ull hv = pk2(hnA, hnB);
        *(ull*)&hw[gr * 8 + bg * 2] = hv;
        st_cl64(ra0 + roff, hv); st_cl64(ra1 + roff, hv); st_cl64(ra2 + roff, hv);
        cluster_sync_();
        p ^= 1;
    }
    // after 64 steps, final h is in hbuf0
    {
        int b = b0 + (int)r * 2;
        g_hT[(size_t)b * HDIM + tid]       = hbuf0[tid * 8 + (int)r * 2];
        g_hT[(size_t)(b + 1) * HDIM + tid] = hbuf0[tid * 8 + (int)r * 2 + 1];
    }
}

// ============================================================
// Encoder head: mu, logsigma, z, h0. grid=B (32), 256 threads.
// ============================================================
__global__ __launch_bounds__(256) void enc_head(
    const float* __restrict__ mu_w,  const float* __restrict__ mu_b,
    const float* __restrict__ ls_w,  const float* __restrict__ ls_b,
    const float* __restrict__ refc_w, const float* __restrict__ refc_b,
    const float* __restrict__ eps,   float* __restrict__ out)
{
    int b = blockIdx.x;
    int u = threadIdx.x;
    __shared__ float hT[HDIM];
    __shared__ float zv[ZDIM];
    hT[u] = g_hT[(size_t)b * HDIM + u];
    __syncthreads();
    if (u < ZDIM) {
        const float* mw = mu_w + u * HDIM;
        const float* lw = ls_w + u * HDIM;
        float am = mu_b[u], al = ls_b[u];
#pragma unroll 8
        for (int k = 0; k < HDIM; k++) { am += mw[k] * hT[k]; al += lw[k] * hT[k]; }
        out[BDIM * TDIM * DDIM + b * ZDIM + u] = am;
        out[BDIM * TDIM * DDIM + BDIM * ZDIM + b * ZDIM + u] = al;
        zv[u] = am + eps[b * ZDIM + u] * __expf(al);
    }
    __syncthreads();
    {
        float acc = refc_b[u];
        const float* rw = refc_w + u * ZDIM;
#pragma unroll 8
        for (int j = 0; j < ZDIM; j++) acc += rw[j] * zv[j];
        g_h0[(size_t)b * HDIM + u] = tanhf_(acc);
    }
}

// ============================================================
// Decoder GRU: 32 clusters of 4 CTAs (128 CTAs). (unchanged from R6)
// SMEM: w_rz 128K | w_n 64K | h 32K | fcw 1K => 230400 B
// ============================================================
#define DSM_WN  131072
#define DSM_H   196608
#define DSM_FCW 229376
#define DSM_TOT 230400
__global__ __launch_bounds__(256, 1) __cluster_dims__(4, 1, 1)
void dec_gru_cl(
    const float* __restrict__ bih_all, const float* __restrict__ bhh_all,
    const float* __restrict__ fcw_all, const float* __restrict__ fcb_all,
    float* __restrict__ out)
{
    extern __shared__ char smem_d[];
    float4* w_rz = (float4*)smem_d;              // [k2][64]
    float4* w_n  = (float4*)(smem_d + DSM_WN);   // [k4][64]
    float*  h_s  = (float*)(smem_d + DSM_H);     // [256][32]
    float*  fcw_s= (float*)(smem_d + DSM_FCW);   // [256]
    __shared__ float wsum[8][8];

    int d = blockIdx.x >> 2;
    uint32_t r = ctarank_();
    int tid = threadIdx.x;
    int ul = tid >> 2, bg = tid & 3;
    int gr = (int)r * 64 + ul;

    {
        const float4* src_rz = g_Drz + (size_t)d * 128 * 256;
        for (int i = tid; i < 128 * 64; i += 256) {
            int k2 = i >> 6, uu = i & 63;
            w_rz[k2 * 64 + uu] = src_rz[(size_t)k2 * 256 + (int)r * 64 + uu];
        }
        const float4* src_n = g_Dn4 + (size_t)d * 64 * 256;
        for (int i = tid; i < 64 * 64; i += 256) {
            int k4 = i >> 6, uu = i & 63;
            w_n[k4 * 64 + uu] = src_n[(size_t)k4 * 256 + (int)r * 64 + uu];
        }
        fcw_s[tid] = fcw_all[d * HDIM + tid];
        for (int i = tid; i < 256 * 32; i += 256) {
            int uu = i >> 5, bb = i & 31;
            h_s[uu * 32 + bb] = g_h0[(size_t)bb * HDIM + uu];
        }
    }
    const float* bih = bih_all + d * G3;
    const float* bhh = bhh_all + d * G3;
    float br  = bih[gr] + bhh[gr];
    float bz  = bih[gr + HDIM] + bhh[gr + HDIM];
    float bni = bih[gr + 2 * HDIM];
    float bnh = bhh[gr + 2 * HDIM];
    float fcb = fcb_all[d];

    float hold[8];
#pragma unroll
    for (int bb = 0; bb < 8; bb++) hold[bb] = g_h0[(size_t)(bg * 8 + bb) * HDIM + gr];

    uint32_t hoff = s2u(&h_s[gr * 32 + bg * 8]);
    uint32_t ra0, ra1, ra2;
    {
        uint32_t tmp[3]; int nr = 0;
        for (uint32_t c = 0; c < 4; c++) if (c != r) tmp[nr++] = mapa_(hoff, c);
        ra0 = tmp[0]; ra1 = tmp[1]; ra2 = tmp[2];
    }
    __syncthreads();

    const float* gi_base = g_decGi + ((size_t)d * TDIM * G3) * BDIM + (size_t)gr * BDIM + bg * 8;

    for (int t = 0; t < TDIM; t++) {
        const float* gp = gi_base + (size_t)t * G3 * BDIM;
        float4 gR0 = *(const float4*)(gp);
        float4 gR1 = *(const float4*)(gp + 4);
        float4 gZ0 = *(const float4*)(gp + 256 * BDIM);
        float4 gZ1 = *(const float4*)(gp + 256 * BDIM + 4);
        float4 gN0 = *(const float4*)(gp + 512 * BDIM);
        float4 gN1 = *(const float4*)(gp + 512 * BDIM + 4);

        ull aR[4] = {0,0,0,0}, aZ[4] = {0,0,0,0}, aN[4] = {0,0,0,0};
#pragma unroll 8
        for (int k4 = 0; k4 < 64; k4++) {
            float4 rzA = w_rz[(2 * k4) * 64 + ul];
            float4 rzB = w_rz[(2 * k4 + 1) * 64 + ul];
            float4 nn  = w_n[k4 * 64 + ul];
            const ulonglong2* hp0 = (const ulonglong2*)&h_s[(k4 * 4 + 0) * 32 + bg * 8];
            const ulonglong2* hp1 = (const ulonglong2*)&h_s[(k4 * 4 + 1) * 32 + bg * 8];
            const ulonglong2* hp2 = (const ulonglong2*)&h_s[(k4 * 4 + 2) * 32 + bg * 8];
            const ulonglong2* hp3 = (const ulonglong2*)&h_s[(k4 * 4 + 3) * 32 + bg * 8];
            {
                ulonglong2 hA = hp0[0], hB = hp0[1];
                ull wr = pk2(rzA.x, rzA.x), wz = pk2(rzA.y, rzA.y), wn = pk2(nn.x, nn.x);
                ffma2(aR[0], wr, hA.x); ffma2(aR[1], wr, hA.y); ffma2(aR[2], wr, hB.x); ffma2(aR[3], wr, hB.y);
                ffma2(aZ[0], wz, hA.x); ffma2(aZ[1], wz, hA.y); ffma2(aZ[2], wz, hB.x); ffma2(aZ[3], wz, hB.y);
                ffma2(aN[0], wn, hA.x); ffma2(aN[1], wn, hA.y); ffma2(aN[2], wn, hB.x); ffma2(aN[3], wn, hB.y);
            }
            {
                ulonglong2 hA = hp1[0], hB = hp1[1];
                ull wr = pk2(rzA.z, rzA.z), wz = pk2(rzA.w, rzA.w), wn = pk2(nn.y, nn.y);
                ffma2(aR[0], wr, hA.x); ffma2(aR[1], wr, hA.y); ffma2(aR[2], wr, hB.x); ffma2(aR[3], wr, hB.y);
                ffma2(aZ[0], wz, hA.x); ffma2(aZ[1], wz, hA.y); ffma2(aZ[2], wz, hB.x); ffma2(aZ[3], wz, hB.y);
                ffma2(aN[0], wn, hA.x); ffma2(aN[1], wn, hA.y); ffma2(aN[2], wn, hB.x); ffma2(aN[3], wn, hB.y);
            }
            {
                ulonglong2 hA = hp2[0], hB = hp2[1];
                ull wr = pk2(rzB.x, rzB.x), wz = pk2(rzB.y, rzB.y), wn = pk2(nn.z, nn.z);
                ffma2(aR[0], wr, hA.x); ffma2(aR[1], wr, hA.y); ffma2(aR[2], wr, hB.x); ffma2(aR[3], wr, hB.y);
                ffma2(aZ[0], wz, hA.x); ffma2(aZ[1], wz, hA.y); ffma2(aZ[2], wz, hB.x); ffma2(aZ[3], wz, hB.y);
                ffma2(aN[0], wn, hA.x); ffma2(aN[1], wn, hA.y); ffma2(aN[2], wn, hB.x); ffma2(aN[3], wn, hB.y);
            }
            {
                ulonglong2 hA = hp3[0], hB = hp3[1];
                ull wr = pk2(rzB.z, rzB.z), wz = pk2(rzB.w, rzB.w), wn = pk2(nn.w, nn.w);
                ffma2(aR[0], wr, hA.x); ffma2(aR[1], wr, hA.y); ffma2(aR[2], wr, hB.x); ffma2(aR[3], wr, hB.y);
                ffma2(aZ[0], wz, hA.x); ffma2(aZ[1], wz, hA.y); ffma2(aZ[2], wz, hB.x); ffma2(aZ[3], wz, hB.y);
                ffma2(aN[0], wn, hA.x); ffma2(aN[1], wn, hA.y); ffma2(aN[2], wn, hB.x); ffma2(aN[3], wn, hB.y);
            }
        }

        float gR[8] = {gR0.x,gR0.y,gR0.z,gR0.w,gR1.x,gR1.y,gR1.z,gR1.w};
        float gZ[8] = {gZ0.x,gZ0.y,gZ0.z,gZ0.w,gZ1.x,gZ1.y,gZ1.z,gZ1.w};
        float gN[8] = {gN0.x,gN0.y,gN0.z,gN0.w,gN1.x,gN1.y,gN1.z,gN1.w};
        float hn[8];
#pragma unroll
        for (int p = 0; p < 4; p++) {
            float2 sR = upk2(aR[p]), sZ = upk2(aZ[p]), sN = upk2(aN[p]);
            float rA = sigmoidf_(gR[2*p]   + br + sR.x);
            float rB = sigmoidf_(gR[2*p+1] + br + sR.y);
            float uA = sigmoidf_(gZ[2*p]   + bz + sZ.x);
            float uB = sigmoidf_(gZ[2*p+1] + bz + sZ.y);
            float nA = tanhf_(gN[2*p]   + bni + rA * (sN.x + bnh));
            float nB = tanhf_(gN[2*p+1] + bni + rB * (sN.y + bnh));
            hn[2*p]   = (1.0f - uA) * nA + uA * hold[2*p];
            hn[2*p+1] = (1.0f - uB) * nB + uB * hold[2*p+1];
        }
#pragma unroll
        for (int bb = 0; bb < 8; bb++) hold[bb] = hn[bb];

        cluster_sync_();
        ull h01 = pk2(hn[0], hn[1]), h23 = pk2(hn[2], hn[3]);
        ull h45 = pk2(hn[4], hn[5]), h67 = pk2(hn[6], hn[7]);
        ull* lp = (ull*)&h_s[gr * 32 + bg * 8];
        lp[0] = h01; lp[1] = h23; lp[2] = h45; lp[3] = h67;
        st_cl64(ra0,      h01); st_cl64(ra0 + 8,  h23); st_cl64(ra0 + 16, h45); st_cl64(ra0 + 24, h67);
        st_cl64(ra1,      h01); st_cl64(ra1 + 8,  h23); st_cl64(ra1 + 16, h45); st_cl64(ra1 + 24, h67);
        st_cl64(ra2,      h01); st_cl64(ra2 + 8,  h23); st_cl64(ra2 + 16, h45); st_cl64(ra2 + 24, h67);
        cluster_sync_();

        {
            float4 ha = *(const float4*)&h_s[tid * 32 + (int)r * 8];
            float4 hb = *(const float4*)&h_s[tid * 32 + (int)r * 8 + 4];
            float pr[8] = {ha.x, ha.y, ha.z, ha.w, hb.x, hb.y, hb.z, hb.w};
            float fw = fcw_s[tid];
#pragma unroll
            for (int bb = 0; bb < 8; bb++) pr[bb] *= fw;
#pragma unroll
            for (int off = 16; off; off >>= 1) {
#pragma unroll
                for (int bb = 0; bb < 8; bb++)
                    pr[bb] += __shfl_xor_sync(0xffffffff, pr[bb], off);
            }
            if ((tid & 31) == 0) {
                int w = tid >> 5;
#pragma unroll
                for (int bb = 0; bb < 8; bb++) wsum[w][bb] = pr[bb];
            }
            __syncthreads();
            if (tid < 8) {
                float s = fcb;
#pragma unroll
                for (int w = 0; w < 8; w++) s += wsum[w][tid];
                int b = (int)r * 8 + tid;
                out[((size_t)b * TDIM + t) * DDIM + d] = s;
            }
        }
    }
}

// ============================================================
// launch — multi-stream DAG (capture-legal fork/join via events)
// ============================================================
extern "C" void kernel_launch(void* const* d_in, const int* in_sizes, int n_in,
                              void* d_out, int out_size)
{
    const float* x_past   = (const float*)d_in[0];
    const float* x_current= (const float*)d_in[1];
    const float* eps      = (const float*)d_in[2];
    const float* enc_Wih  = (const float*)d_in[3];
    const float* enc_bih  = (const float*)d_in[4];
    const float* enc_Whh  = (const float*)d_in[5];
    const float* enc_bhh  = (const float*)d_in[6];
    const float* enc_mu_w = (const float*)d_in[7];
    const float* enc_mu_b = (const float*)d_in[8];
    const float* enc_ls_w = (const float*)d_in[9];
    const float* enc_ls_b = (const float*)d_in[10];
    const float* refc_w   = (const float*)d_in[11];
    const float* refc_b   = (const float*)d_in[12];
    const float* Win      = (const float*)d_in[13];
    const float* h_Wih    = (const float*)d_in[14];
    const float* h_bih    = (const float*)d_in[15];
    const float* h_Whh    = (const float*)d_in[16];
    const float* h_bhh    = (const float*)d_in[17];
    const float* fc_w     = (const float*)d_in[18];
    const float* fc_b     = (const float*)d_in[19];
    float* out = (float*)d_out;

    float4 *dErz, *dEn4, *dDrz, *dDn4;
    cudaGetSymbolAddress((void**)&dErz, g_Erz);
    cudaGetSymbolAddress((void**)&dEn4, g_En4);
    cudaGetSymbolAddress((void**)&dDrz, g_Drz);
    cudaGetSymbolAddress((void**)&dDn4, g_Dn4);

    static cudaStream_t s1 = nullptr, s2 = nullptr;
    static cudaEvent_t eF = nullptr, e1 = nullptr, e2 = nullptr;
    if (!s1) {
        cudaStreamCreateWithFlags(&s1, cudaStreamNonBlocking);
        cudaStreamCreateWithFlags(&s2, cudaStreamNonBlocking);
        cudaEventCreateWithFlags(&eF, cudaEventDisableTiming);
        cudaEventCreateWithFlags(&e1, cudaEventDisableTiming);
        cudaEventCreateWithFlags(&e2, cudaEventDisableTiming);
        cudaFuncSetAttribute(prep_decgi, cudaFuncAttributeMaxDynamicSharedMemorySize,
                             G3 * WS_PITCH * 4 + DDIM * DIN_PITCH * 4);
        cudaFuncSetAttribute(enc_gru_cl, cudaFuncAttributeMaxDynamicSharedMemorySize, ESM_TOT);
        cudaFuncSetAttribute(dec_gru_cl, cudaFuncAttributeMaxDynamicSharedMemorySize, DSM_TOT);
    }

    // fork side streams off the capture-origin (legacy) stream
    cudaEventRecord(eF, 0);
    cudaStreamWaitEvent(s1, eF, 0);
    cudaStreamWaitEvent(s2, eF, 0);

    // origin stream: encoder chain
    prep_encgi<<<BDIM * TDIM, 256>>>(x_past, enc_Wih, enc_bih);          // #1
    prep_trans<<<64, 256>>>(enc_Whh, dErz, dEn4);                        // #2
    // s1: decoder input-gate chain (independent of encoder)
    prep_wcomb<<<DDIM * 96, 256, 0, s1>>>(Win, h_Wih);                   // #3
    enc_gru_cl<<<16, 256, ESM_TOT>>>(enc_bhh);                           // #4 (profiled)
    prep_decgi<<<DDIM * 8, 256,
                 G3 * WS_PITCH * 4 + DDIM * DIN_PITCH * 4, s1>>>(x_past, x_current); // #5
    // s2: decoder weight transpose
    prep_trans<<<DDIM * 64, 256, 0, s2>>>(h_Whh, dDrz, dDn4);            // #6
    enc_head<<<BDIM, 256>>>(enc_mu_w, enc_mu_b, enc_ls_w, enc_ls_b,
                            refc_w, refc_b, eps, out);                   // #7

    // join
    cudaEventRecord(e1, s1);
    cudaEventRecord(e2, s2);
    cudaStreamWaitEvent(0, e1, 0);
    cudaStreamWaitEvent(0, e2, 0);
    dec_gru_cl<<<DDIM * 4, 256, DSM_TOT>>>(h_bih, h_bhh, fc_w, fc_b, out); // #8
}